// round 15
// baseline (speedup 1.0000x reference)
#include <cuda_runtime.h>
#include <cuda_bf16.h>
#include <math.h>

// ---------------- scratch (device globals; no runtime allocation) -------------
__device__ float g_h[(size_t)50000 * 512];
__device__ float g_as[50000 * 8];
__device__ float g_ad[50000 * 8];
__device__ float g_f1[50000 * 64];
__device__ float g_f2[50000 * 64];
__device__ int   g_deg[50000];
__device__ int   g_rowptr[50001];
__device__ int   g_wp[50000];
__device__ int   g_col[450000];
__device__ int   g_is32;
__device__ int   g_bsum[128];
__device__ int   g_boff[128];
__device__ __nv_bfloat16 g_ahi[(size_t)50000 * 256];
__device__ __nv_bfloat16 g_alo[(size_t)50000 * 256];
__device__ __nv_bfloat16 g_bhi[256 * 512];
__device__ __nv_bfloat16 g_blo[256 * 512];

__device__ __forceinline__ float* selbuf(int s) {
    if (s == 0) return g_h;
    if (s == 1) return g_f1;
    return g_f2;
}

__device__ __forceinline__ int edge_at(const void* ei, long long idx, int is32) {
    return is32 ? ((const int*)ei)[idx] : (int)((const long long*)ei)[idx];
}

// ---------------- dtype detection ------------
__global__ void k_detect(const void* __restrict__ ei, int n) {
    if (threadIdx.x != 0 || blockIdx.x != 0) return;
    const long long* p = (const long long*)ei;
    int bad = 0;
    for (int i = 0; i < 64; i++) {
        long long v = p[i];
        if (v < 0 || v >= (long long)n) bad = 1;
    }
    g_is32 = bad;
}

// ---------------- CSR build -------------
__global__ void k_initdeg(int n) {
    int i = blockIdx.x * blockDim.x + threadIdx.x;
    if (i < n) g_deg[i] = 1;
}

__global__ void k_hist(const void* __restrict__ ei, int E, int n) {
    int i = blockIdx.x * blockDim.x + threadIdx.x;
    if (i >= E) return;
    int v = edge_at(ei, (long long)E + i, g_is32);
    if ((unsigned)v < (unsigned)n) atomicAdd(&g_deg[v], 1);
}

__global__ void k_scanA(int n) {
    __shared__ int sh[32];
    int t = threadIdx.x;
    int idx = blockIdx.x * 1024 + t;
    int v = (idx < n) ? g_deg[idx] : 0;
    int x = v;
    #pragma unroll
    for (int o = 1; o < 32; o <<= 1) {
        int y = __shfl_up_sync(0xffffffffu, x, o);
        if ((t & 31) >= o) x += y;
    }
    if ((t & 31) == 31) sh[t >> 5] = x;
    __syncthreads();
    if (t < 32) {
        int y = sh[t];
        #pragma unroll
        for (int o = 1; o < 32; o <<= 1) {
            int z = __shfl_up_sync(0xffffffffu, y, o);
            if (t >= o) y += z;
        }
        sh[t] = y;
    }
    __syncthreads();
    int off = ((t >> 5) > 0) ? sh[(t >> 5) - 1] : 0;
    int excl = x - v + off;
    if (idx < n) g_rowptr[idx] = excl;
    if (t == 1023) g_bsum[blockIdx.x] = excl + v;
}

__global__ void k_scanB(int nb, int n) {
    if (threadIdx.x != 0) return;
    int acc = 0;
    for (int i = 0; i < nb; i++) { int x = g_bsum[i]; g_boff[i] = acc; acc += x; }
    g_rowptr[n] = acc;
}

__global__ void k_scanC(int n) {
    int idx = blockIdx.x * blockDim.x + threadIdx.x;
    if (idx >= n) return;
    int v = g_rowptr[idx] + g_boff[idx >> 10];
    g_rowptr[idx] = v;
    g_wp[idx] = v;
}

__global__ void k_fill(const void* __restrict__ ei, int E, int n) {
    int i = blockIdx.x * blockDim.x + threadIdx.x;
    if (i >= E + n) return;
    int is32 = g_is32;
    int v, s;
    if (i < E) {
        s = edge_at(ei, i, is32);
        v = edge_at(ei, (long long)E + i, is32);
    } else {
        v = s = i - E;
    }
    if ((unsigned)v >= (unsigned)n || (unsigned)s >= (unsigned)n) return;
    int p = atomicAdd(&g_wp[v], 1);
    if ((unsigned)p < (unsigned)(E + n)) g_col[p] = s;
}

// ---------------- bf16 split conversion (float4-vectorized) ----------------
__global__ void k_cvtA(const float* __restrict__ src, int srcsel, int count4) {
    int i = blockIdx.x * blockDim.x + threadIdx.x;
    if (i >= count4) return;
    const float* s = (srcsel < 0) ? src : selbuf(srcsel);
    float4 v = ((const float4*)s)[i];
    __nv_bfloat16 h0 = __float2bfloat16(v.x), h1 = __float2bfloat16(v.y);
    __nv_bfloat16 h2 = __float2bfloat16(v.z), h3 = __float2bfloat16(v.w);
    __nv_bfloat162* ph = (__nv_bfloat162*)g_ahi;
    __nv_bfloat162* pl = (__nv_bfloat162*)g_alo;
    ph[i * 2 + 0] = __nv_bfloat162(h0, h1);
    ph[i * 2 + 1] = __nv_bfloat162(h2, h3);
    pl[i * 2 + 0] = __nv_bfloat162(
        __float2bfloat16(v.x - __bfloat162float(h0)),
        __float2bfloat16(v.y - __bfloat162float(h1)));
    pl[i * 2 + 1] = __nv_bfloat162(
        __float2bfloat16(v.z - __bfloat162float(h2)),
        __float2bfloat16(v.w - __bfloat162float(h3)));
}

__global__ void k_cvtB(const float* __restrict__ src, int count4) {
    int i = blockIdx.x * blockDim.x + threadIdx.x;
    if (i >= count4) return;
    float4 v = ((const float4*)src)[i];
    __nv_bfloat16 h0 = __float2bfloat16(v.x), h1 = __float2bfloat16(v.y);
    __nv_bfloat16 h2 = __float2bfloat16(v.z), h3 = __float2bfloat16(v.w);
    __nv_bfloat162* ph = (__nv_bfloat162*)g_bhi;
    __nv_bfloat162* pl = (__nv_bfloat162*)g_blo;
    ph[i * 2 + 0] = __nv_bfloat162(h0, h1);
    ph[i * 2 + 1] = __nv_bfloat162(h2, h3);
    pl[i * 2 + 0] = __nv_bfloat162(
        __float2bfloat16(v.x - __bfloat162float(h0)),
        __float2bfloat16(v.y - __bfloat162float(h1)));
    pl[i * 2 + 1] = __nv_bfloat162(
        __float2bfloat16(v.z - __bfloat162float(h2)),
        __float2bfloat16(v.w - __bfloat162float(h3)));
}

// ---------------- bf16 tensor-core GEMM (fused split fp32, cp.async, BK=32) ----
__device__ __forceinline__ void mma_bf16(float* d, const unsigned* a, const unsigned* b) {
    asm volatile(
        "mma.sync.aligned.m16n8k16.row.col.f32.bf16.bf16.f32 "
        "{%0,%1,%2,%3},{%4,%5,%6,%7},{%8,%9},{%0,%1,%2,%3};\n"
        : "+f"(d[0]), "+f"(d[1]), "+f"(d[2]), "+f"(d[3])
        : "r"(a[0]), "r"(a[1]), "r"(a[2]), "r"(a[3]), "r"(b[0]), "r"(b[1]));
}
__device__ __forceinline__ void ldsm_x4(unsigned* r, unsigned addr) {
    asm volatile("ldmatrix.sync.aligned.m8n8.x4.shared.b16 {%0,%1,%2,%3},[%4];"
        : "=r"(r[0]), "=r"(r[1]), "=r"(r[2]), "=r"(r[3]) : "r"(addr));
}
__device__ __forceinline__ void ldsm_x2t(unsigned* r, unsigned addr) {
    asm volatile("ldmatrix.sync.aligned.m8n8.x2.trans.shared.b16 {%0,%1},[%2];"
        : "=r"(r[0]), "=r"(r[1]) : "r"(addr));
}
__device__ __forceinline__ void cp16(unsigned dst, const void* src, int nbytes) {
    asm volatile("cp.async.cg.shared.global [%0], [%1], 16, %2;"
        :: "r"(dst), "l"(src), "r"(nbytes));
}

#define ASTRIDE 80   // 32 bf16 = 64B + 16B pad

// Generic: BM=128, BK=32, 256 threads (8 warps). Dynamic smem double buffer.
// BN=128: warps 2x4; BN=64: warps 4x2. Optional bias/relu; optional attn epilogue.
template <int BN, bool BIAS, bool RELU>
__global__ void __launch_bounds__(256, 2) k_bmma(
        const float* __restrict__ atts, const float* __restrict__ attd,
        const float* __restrict__ bias,
        int H, int csel, int M, int N, int K) {
    constexpr int BSTRIDE = BN * 2 + 16;
    constexpr int WM = (BN == 128) ? 2 : 4;
    constexpr int WN = 8 / WM;
    constexpr int MT = 128 / WM / 16;
    constexpr int NT = BN / WN / 8;
    constexpr int RPW = 128 / WM;
    constexpr int CPW = BN / WN;
    constexpr int ABUF = 128 * ASTRIDE;       // bytes per A buffer
    constexpr int BBUF = 32 * BSTRIDE;        // bytes per B buffer
    constexpr int BCPR = BN / 8;              // B 16B-chunks per row
    constexpr int BPER = BN / 64;             // B chunks per thread (2 or 1)
    constexpr int HPC = BN / 64;

    float* __restrict__ C = selbuf(csel);
    extern __shared__ __align__(16) unsigned char dyn[];
    unsigned char* smAhi = dyn;
    unsigned char* smAlo = smAhi + 2 * ABUF;
    unsigned char* smBhi = smAlo + 2 * ABUF;
    unsigned char* smBlo = smBhi + 2 * BBUF;
    __shared__ float s_att[2][BN];
    __shared__ float red[2][128][2];

    const int tid = threadIdx.x, lane = tid & 31, wid = tid >> 5;
    const int wm = wid % WM, wn = wid / WM;
    const int bm = blockIdx.y * 128, bn = blockIdx.x * BN;
    const int ktiles = K / 32;

    float acc[MT][NT][4];
    #pragma unroll
    for (int i = 0; i < MT; i++)
        #pragma unroll
        for (int j = 0; j < NT; j++)
            #pragma unroll
            for (int q = 0; q < 4; q++) acc[i][j][q] = 0.f;

    const int a_r = tid >> 1;                 // row (2 chunks per thread, same row)
    const int a_gm = bm + a_r;
    const int a_nb = (a_gm < M) ? 16 : 0;
    const int a_gmc = (a_gm < M) ? a_gm : 0;

    auto loadTile = [&](int buf, int kt) {
        int k0 = kt * 32;
        #pragma unroll
        for (int i = 0; i < 2; i++) {
            int cc = 2 * (tid & 1) + i;       // 0..3
            size_t aoff = (size_t)a_gmc * K + k0 + cc * 8;
            unsigned dA = buf * ABUF + a_r * ASTRIDE + cc * 16;
            cp16((unsigned)__cvta_generic_to_shared(smAhi) + dA, g_ahi + aoff, a_nb);
            cp16((unsigned)__cvta_generic_to_shared(smAlo) + dA, g_alo + aoff, a_nb);
        }
        #pragma unroll
        for (int i = 0; i < BPER; i++) {
            int c = tid * BPER + i;
            int r = c / BCPR, cc = c % BCPR;
            int gn = bn + cc * 8;
            int bnb = (gn < N) ? 16 : 0;
            size_t boff = (size_t)(k0 + r) * N + gn;
            unsigned dB = buf * BBUF + r * BSTRIDE + cc * 16;
            cp16((unsigned)__cvta_generic_to_shared(smBhi) + dB, g_bhi + boff, bnb);
            cp16((unsigned)__cvta_generic_to_shared(smBlo) + dB, g_blo + boff, bnb);
        }
        asm volatile("cp.async.commit_group;" ::: "memory");
    };

    const int arow = (lane & 7) + ((lane >> 3) & 1) * 8;
    const int ahalf = (lane >> 4) * 8;
    const int bk = lane & 15;

    loadTile(0, 0);

    for (int it = 0; it < ktiles; it++) {
        int buf = it & 1;
        asm volatile("cp.async.wait_group 0;" ::: "memory");
        __syncthreads();
        if (it + 1 < ktiles) loadTile(buf ^ 1, it + 1);

        unsigned aHiB = (unsigned)__cvta_generic_to_shared(smAhi) + buf * ABUF;
        unsigned aLoB = (unsigned)__cvta_generic_to_shared(smAlo) + buf * ABUF;
        unsigned bHiB = (unsigned)__cvta_generic_to_shared(smBhi) + buf * BBUF;
        unsigned bLoB = (unsigned)__cvta_generic_to_shared(smBlo) + buf * BBUF;

        #pragma unroll
        for (int kt2 = 0; kt2 < 2; kt2++) {
            unsigned aoff = (wm * RPW + arow) * ASTRIDE + (kt2 * 16 + ahalf) * 2;
            unsigned boff = (kt2 * 16 + bk) * BSTRIDE + (wn * CPW) * 2;

            unsigned ahi[MT][4], bhi[NT][2];
            #pragma unroll
            for (int mt = 0; mt < MT; mt++)
                ldsm_x4(ahi[mt], aHiB + aoff + mt * 16 * ASTRIDE);
            #pragma unroll
            for (int nt = 0; nt < NT; nt++)
                ldsm_x2t(bhi[nt], bHiB + boff + nt * 16);
            #pragma unroll
            for (int mt = 0; mt < MT; mt++)
                #pragma unroll
                for (int nt = 0; nt < NT; nt++)
                    mma_bf16(acc[mt][nt], ahi[mt], bhi[nt]);

            unsigned blo[NT][2];
            #pragma unroll
            for (int nt = 0; nt < NT; nt++)
                ldsm_x2t(blo[nt], bLoB + boff + nt * 16);
            #pragma unroll
            for (int mt = 0; mt < MT; mt++)
                #pragma unroll
                for (int nt = 0; nt < NT; nt++)
                    mma_bf16(acc[mt][nt], ahi[mt], blo[nt]);

            unsigned alo[MT][4];
            #pragma unroll
            for (int mt = 0; mt < MT; mt++)
                ldsm_x4(alo[mt], aLoB + aoff + mt * 16 * ASTRIDE);
            #pragma unroll
            for (int mt = 0; mt < MT; mt++)
                #pragma unroll
                for (int nt = 0; nt < NT; nt++)
                    mma_bf16(acc[mt][nt], alo[mt], bhi[nt]);
        }
        // no trailing sync: next iteration's top barrier orders compute(it)
        // before any cp.async that overwrites this buffer (issued at it+1).
    }

    #pragma unroll
    for (int mt = 0; mt < MT; mt++) {
        int r0 = bm + wm * RPW + mt * 16 + (lane >> 2);
        #pragma unroll
        for (int nt = 0; nt < NT; nt++) {
            int cn = bn + wn * CPW + nt * 8 + (lane & 3) * 2;
            if (cn >= N) continue;
            float b0 = 0.f, b1 = 0.f;
            if (BIAS) { b0 = bias[cn]; b1 = bias[cn + 1]; }
            #pragma unroll
            for (int half = 0; half < 2; half++) {
                int r = r0 + half * 8;
                if (r >= M) continue;
                float y0 = acc[mt][nt][half * 2 + 0] + b0;
                float y1 = acc[mt][nt][half * 2 + 1] + b1;
                if (RELU) { y0 = fmaxf(y0, 0.f); y1 = fmaxf(y1, 0.f); }
                *(float2*)(C + (size_t)r * N + cn) = make_float2(y0, y1);
            }
        }
    }

    if (atts != nullptr) {
        if (tid < BN) {
            s_att[0][tid] = atts[bn + tid];
            s_att[1][tid] = attd[bn + tid];
        }
        if (tid < 256) {
            red[0][tid >> 1][tid & 1] = 0.f;
            red[1][tid >> 1][tid & 1] = 0.f;
        }
        __syncthreads();
        int hloc = (wn * CPW) >> 6;
        #pragma unroll
        for (int mt = 0; mt < MT; mt++) {
            #pragma unroll
            for (int half = 0; half < 2; half++) {
                float ps = 0.f, pd = 0.f;
                #pragma unroll
                for (int nt = 0; nt < NT; nt++) {
                    #pragma unroll
                    for (int e = 0; e < 2; e++) {
                        int cl = wn * CPW + nt * 8 + (lane & 3) * 2 + e;
                        float v = acc[mt][nt][half * 2 + e];
                        ps += v * s_att[0][cl];
                        pd += v * s_att[1][cl];
                    }
                }
                ps += __shfl_xor_sync(0xffffffffu, ps, 1);
                ps += __shfl_xor_sync(0xffffffffu, ps, 2);
                pd += __shfl_xor_sync(0xffffffffu, pd, 1);
                pd += __shfl_xor_sync(0xffffffffu, pd, 2);
                if ((lane & 3) == 0) {
                    int rl = wm * RPW + mt * 16 + half * 8 + (lane >> 2);
                    atomicAdd(&red[0][rl][hloc], ps);
                    atomicAdd(&red[1][rl][hloc], pd);
                }
            }
        }
        __syncthreads();
        if (tid < 128) {
            int node = bm + tid;
            if (node < M) {
                int hb = bn >> 6;
                #pragma unroll
                for (int hh = 0; hh < HPC; hh++) {
                    g_as[node * H + hb + hh] = red[0][tid][hh];
                    g_ad[node * H + hb + hh] = red[1][tid][hh];
                }
            }
        }
    }
}

// ---------------- fp32 SGEMM (+optional fused row softmax) ----------------
template <bool BIAS, bool RELU, bool SMAX>
__global__ void k_sgemm(const float* __restrict__ Aext, const float* __restrict__ B,
                        const float* __restrict__ bias, float* __restrict__ outp,
                        int asel, int csel, int M, int N, int K) {
    const float* __restrict__ A = (asel < 0) ? Aext : selbuf(asel);
    float* __restrict__ C = selbuf(csel);
    __shared__ float As[16][68];
    __shared__ float Bs[16][68];
    int tid = threadIdx.x;
    int ty = tid >> 4, tx = tid & 15;
    int bm = blockIdx.y * 64, bn = blockIdx.x * 64;
    int ar = tid >> 2, ac = (tid & 3) << 2;
    int br = tid >> 4, bc = (tid & 15) << 2;
    float acc[4][4];
    #pragma unroll
    for (int i = 0; i < 4; i++)
        #pragma unroll
        for (int j = 0; j < 4; j++) acc[i][j] = 0.f;

    for (int k0 = 0; k0 < K; k0 += 16) {
        int gm = bm + ar;
        float4 av = make_float4(0.f, 0.f, 0.f, 0.f);
        if (gm < M) av = *(const float4*)(A + (size_t)gm * K + k0 + ac);
        As[ac + 0][ar] = av.x; As[ac + 1][ar] = av.y;
        As[ac + 2][ar] = av.z; As[ac + 3][ar] = av.w;

        int gk = k0 + br, gn = bn + bc;
        float4 bv;
        if (((N & 3) == 0) && (gn + 3 < N)) {
            bv = *(const float4*)(B + (size_t)gk * N + gn);
        } else {
            bv.x = (gn + 0 < N) ? B[(size_t)gk * N + gn + 0] : 0.f;
            bv.y = (gn + 1 < N) ? B[(size_t)gk * N + gn + 1] : 0.f;
            bv.z = (gn + 2 < N) ? B[(size_t)gk * N + gn + 2] : 0.f;
            bv.w = (gn + 3 < N) ? B[(size_t)gk * N + gn + 3] : 0.f;
        }
        Bs[br][bc + 0] = bv.x; Bs[br][bc + 1] = bv.y;
        Bs[br][bc + 2] = bv.z; Bs[br][bc + 3] = bv.w;
        __syncthreads();

        #pragma unroll
        for (int kk = 0; kk < 16; kk++) {
            float a[4], b[4];
            #pragma unroll
            for (int i = 0; i < 4; i++) a[i] = As[kk][ty * 4 + i];
            #pragma unroll
            for (int j = 0; j < 4; j++) b[j] = Bs[kk][tx * 4 + j];
            #pragma unroll
            for (int i = 0; i < 4; i++)
                #pragma unroll
                for (int j = 0; j < 4; j++) acc[i][j] += a[i] * b[j];
        }
        __syncthreads();
    }

    if (SMAX) {
        #pragma unroll
        for (int i = 0; i < 4; i++) {
            int row = bm + ty * 4 + i;
            float v[4];
            float mx = -1e30f;
            #pragma unroll
            for (int j = 0; j < 4; j++) {
                int cn = tx * 4 + j;
                v[j] = (cn < N) ? (acc[i][j] + (BIAS ? bias[cn] : 0.f)) : -1e30f;
                mx = fmaxf(mx, v[j]);
            }
            #pragma unroll
            for (int o = 8; o > 0; o >>= 1)
                mx = fmaxf(mx, __shfl_xor_sync(0xffffffffu, mx, o));
            float se = 0.f;
            #pragma unroll
            for (int j = 0; j < 4; j++) {
                v[j] = (tx * 4 + j < N) ? __expf(v[j] - mx) : 0.f;
                se += v[j];
            }
            #pragma unroll
            for (int o = 8; o > 0; o >>= 1)
                se += __shfl_xor_sync(0xffffffffu, se, o);
            float inv = 1.f / se;
            if (row < M) {
                #pragma unroll
                for (int j = 0; j < 4; j++) {
                    int cn = tx * 4 + j;
                    if (cn < N) outp[(size_t)row * N + cn] = v[j] * inv;
                }
            }
        }
    } else {
        #pragma unroll
        for (int i = 0; i < 4; i++) {
            int row = bm + ty * 4 + i;
            if (row >= M) continue;
            #pragma unroll
            for (int j = 0; j < 4; j++) {
                int cn = bn + tx * 4 + j;
                if (cn >= N) continue;
                float v = acc[i][j];
                if (BIAS) v += bias[cn];
                if (RELU) v = fmaxf(v, 0.f);
                C[(size_t)row * N + cn] = v;
            }
        }
    }
}

// ---------------- GAT gather: float4-vectorized, edge-unrolled x2 ----------
template <int H, bool BNRELU, bool SPLIT>
__global__ void k_gather4(const float* __restrict__ bias,
                          const float* __restrict__ bng, const float* __restrict__ bnb,
                          const float* __restrict__ bnm, const float* __restrict__ bnv,
                          int osel, int n) {
    constexpr int Q = H / 2;
    float* __restrict__ out = selbuf(osel);
    int w = (blockIdx.x * blockDim.x + threadIdx.x) >> 5;
    int lane = threadIdx.x & 31;
    if (w >= n) return;
    int start = g_rowptr[w], end = g_rowptr[w + 1];
    int c = lane >> 4;

    float adl[H], m[H];
    #pragma unroll
    for (int h = 0; h < H; h++) { adl[h] = g_ad[w * H + h]; m[h] = -1e30f; }

    for (int j = start + lane; j < end; j += 32) {
        int s = g_col[j];
        #pragma unroll
        for (int h = 0; h < H; h++) {
            float e = g_as[s * H + h] + adl[h];
            e = (e > 0.f) ? e : 0.2f * e;
            m[h] = fmaxf(m[h], e);
        }
    }
    #pragma unroll
    for (int h = 0; h < H; h++)
        #pragma unroll
        for (int o = 16; o > 0; o >>= 1)
            m[h] = fmaxf(m[h], __shfl_xor_sync(0xffffffffu, m[h], o));

    float mq[Q], aq[Q];
    #pragma unroll
    for (int q = 0; q < Q; q++) { mq[q] = m[c + 2 * q]; aq[q] = adl[c + 2 * q]; }

    float4 facc[Q];
    float den[Q];
    #pragma unroll
    for (int q = 0; q < Q; q++) { facc[q] = make_float4(0.f, 0.f, 0.f, 0.f); den[q] = 0.f; }

    int j = start;
    for (; j + 2 <= end; j += 2) {
        int s0 = g_col[j], s1 = g_col[j + 1];
        const float4* h0 = (const float4*)(g_h + (size_t)s0 * (H * 64));
        const float4* h1 = (const float4*)(g_h + (size_t)s1 * (H * 64));
        float w0[Q], w1[Q];
        #pragma unroll
        for (int q = 0; q < Q; q++) {
            float e0 = g_as[s0 * H + c + 2 * q] + aq[q];
            e0 = (e0 > 0.f) ? e0 : 0.2f * e0;
            w0[q] = __expf(e0 - mq[q]);
            float e1 = g_as[s1 * H + c + 2 * q] + aq[q];
            e1 = (e1 > 0.f) ? e1 : 0.2f * e1;
            w1[q] = __expf(e1 - mq[q]);
        }
        float4 v0[Q], v1[Q];
        #pragma unroll
        for (int q = 0; q < Q; q++) { v0[q] = h0[lane + 32 * q]; v1[q] = h1[lane + 32 * q]; }
        #pragma unroll
        for (int q = 0; q < Q; q++) {
            den[q] += w0[q] + w1[q];
            facc[q].x += w0[q] * v0[q].x + w1[q] * v1[q].x;
            facc[q].y += w0[q] * v0[q].y + w1[q] * v1[q].y;
            facc[q].z += w0[q] * v0[q].z + w1[q] * v1[q].z;
            facc[q].w += w0[q] * v0[q].w + w1[q] * v1[q].w;
        }
    }
    if (j < end) {
        int s = g_col[j];
        const float4* hr = (const float4*)(g_h + (size_t)s * (H * 64));
        #pragma unroll
        for (int q = 0; q < Q; q++) {
            float e = g_as[s * H + c + 2 * q] + aq[q];
            e = (e > 0.f) ? e : 0.2f * e;
            float wgt = __expf(e - mq[q]);
            den[q] += wgt;
            float4 v = hr[lane + 32 * q];
            facc[q].x += wgt * v.x; facc[q].y += wgt * v.y;
            facc[q].z += wgt * v.z; facc[q].w += wgt * v.w;
        }
    }

    float4 sum = make_float4(0.f, 0.f, 0.f, 0.f);
    #pragma unroll
    for (int q = 0; q < Q; q++) {
        float inv = 1.f / (den[q] + 1e-16f);
        sum.x += facc[q].x * inv; sum.y += facc[q].y * inv;
        sum.z += facc[q].z * inv; sum.w += facc[q].w * inv;
    }
    sum.x += __shfl_xor_sync(0xffffffffu, sum.x, 16);
    sum.y += __shfl_xor_sync(0xffffffffu, sum.y, 16);
    sum.z += __shfl_xor_sync(0xffffffffu, sum.z, 16);
    sum.w += __shfl_xor_sync(0xffffffffu, sum.w, 16);

    if (c == 0) {
        int ch = (lane & 15) * 4;
        const float invH = 1.f / (float)H;
        float4 bb = *(const float4*)(bias + ch);
        float y[4] = {sum.x * invH + bb.x, sum.y * invH + bb.y,
                      sum.z * invH + bb.z, sum.w * invH + bb.w};
        if (BNRELU) {
            float4 gm_ = *(const float4*)(bng + ch);
            float4 bt = *(const float4*)(bnb + ch);
            float4 mu = *(const float4*)(bnm + ch);
            float4 vr = *(const float4*)(bnv + ch);
            y[0] = fmaxf((y[0] - mu.x) * gm_.x * rsqrtf(vr.x + 1e-5f) + bt.x, 0.f);
            y[1] = fmaxf((y[1] - mu.y) * gm_.y * rsqrtf(vr.y + 1e-5f) + bt.y, 0.f);
            y[2] = fmaxf((y[2] - mu.z) * gm_.z * rsqrtf(vr.z + 1e-5f) + bt.z, 0.f);
            y[3] = fmaxf((y[3] - mu.w) * gm_.w * rsqrtf(vr.w + 1e-5f) + bt.w, 0.f);
        }
        if (SPLIT) {
            size_t base = (size_t)w * 64 + ch;
            #pragma unroll
            for (int k = 0; k < 4; k++) {
                __nv_bfloat16 hi = __float2bfloat16(y[k]);
                g_ahi[base + k] = hi;
                g_alo[base + k] = __float2bfloat16(y[k] - __bfloat162float(hi));
            }
        } else {
            *(float4*)(out + (size_t)w * 64 + ch) = make_float4(y[0], y[1], y[2], y[3]);
        }
    }
}

// ---------------- GAT gather (scalar, H=1; optional SPLIT output) ----------
template <bool SPLIT>
__global__ void k_gather1(const float* __restrict__ bias, int osel, int n) {
    float* __restrict__ out = selbuf(osel);
    int w = (blockIdx.x * blockDim.x + threadIdx.x) >> 5;
    int lane = threadIdx.x & 31;
    if (w >= n) return;
    int start = g_rowptr[w], end = g_rowptr[w + 1];

    float adl = g_ad[w], m = -1e30f;
    for (int j = start + lane; j < end; j += 32) {
        float e = g_as[g_col[j]] + adl;
        e = (e > 0.f) ? e : 0.2f * e;
        m = fmaxf(m, e);
    }
    #pragma unroll
    for (int o = 16; o > 0; o >>= 1)
        m = fmaxf(m, __shfl_xor_sync(0xffffffffu, m, o));

    float a0 = 0.f, a1 = 0.f, den = 0.f;
    for (int j = start; j < end; j++) {
        int s = g_col[j];
        float e = g_as[s] + adl;
        e = (e > 0.f) ? e : 0.2f * e;
        float wgt = __expf(e - m);
        den += wgt;
        const float* hr = g_h + (size_t)s * 64;
        a0 += wgt * hr[lane];
        a1 += wgt * hr[lane + 32];
    }
    float inv = 1.f / (den + 1e-16f);
    float y0 = a0 * inv + bias[lane];
    float y1 = a1 * inv + bias[lane + 32];
    if (SPLIT) {
        size_t base = (size_t)w * 64;
        __nv_bfloat16 h0 = __float2bfloat16(y0);
        __nv_bfloat16 h1 = __float2bfloat16(y1);
        g_ahi[base + lane] = h0;
        g_ahi[base + lane + 32] = h1;
        g_alo[base + lane] = __float2bfloat16(y0 - __bfloat162float(h0));
        g_alo[base + lane + 32] = __float2bfloat16(y1 - __bfloat162float(h1));
    } else {
        out[(size_t)w * 64 + lane] = y0;
        out[(size_t)w * 64 + lane + 32] = y1;
    }
}

// ---------------- host orchestration ----------------
extern "C" void kernel_launch(void* const* d_in, const int* in_sizes, int n_in,
                              void* d_out, int out_size) {
    const float* x   = (const float*)d_in[0];
    const void*  ei  = d_in[1];
    const float* W1  = (const float*)d_in[2];
    const float* as1 = (const float*)d_in[3];
    const float* ad1 = (const float*)d_in[4];
    const float* b1  = (const float*)d_in[5];
    const float* W2  = (const float*)d_in[6];
    const float* as2 = (const float*)d_in[7];
    const float* ad2 = (const float*)d_in[8];
    const float* b2  = (const float*)d_in[9];
    const float* W3  = (const float*)d_in[10];
    const float* as3 = (const float*)d_in[11];
    const float* ad3 = (const float*)d_in[12];
    const float* b3  = (const float*)d_in[13];
    const float* bn1g = (const float*)d_in[14];
    const float* bn1b = (const float*)d_in[15];
    const float* bn1m = (const float*)d_in[16];
    const float* bn1v = (const float*)d_in[17];
    const float* bn2g = (const float*)d_in[18];
    const float* bn2b = (const float*)d_in[19];
    const float* bn2m = (const float*)d_in[20];
    const float* bn2v = (const float*)d_in[21];
    const float* cW1 = (const float*)d_in[22];
    const float* cb1 = (const float*)d_in[23];
    const float* cW2 = (const float*)d_in[24];
    const float* cb2 = (const float*)d_in[25];

    int n = in_sizes[0] / 256;   // 50000
    int E = in_sizes[1] / 2;     // 400000
    float* out = (float*)d_out;
    int nblk = (n + 1023) / 1024;

    // dynamic smem sizes (A: 2 buf x 2 split x 128x80; B: 2 x 2 x 32 x stride)
    const int SM128 = 2 * 2 * 128 * 80 + 2 * 2 * 32 * (128 * 2 + 16);  // 75776
    const int SM64  = 2 * 2 * 128 * 80 + 2 * 2 * 32 * (64 * 2 + 16);   // 59392
    cudaFuncSetAttribute(k_bmma<128, false, false>,
                         cudaFuncAttributeMaxDynamicSharedMemorySize, SM128);
    cudaFuncSetAttribute(k_bmma<64, false, false>,
                         cudaFuncAttributeMaxDynamicSharedMemorySize, SM64);
    cudaFuncSetAttribute(k_bmma<64, true, true>,
                         cudaFuncAttributeMaxDynamicSharedMemorySize, SM64);

    // --- layer-1 GEMM first (4th launch = ncu capture slot) ---
    k_cvtA<<<(n * 64 + 255) / 256, 256>>>(x, -1, n * 64);            // 1
    k_cvtB<<<(256 * 128 + 255) / 256, 256>>>(W1, 256 * 128);        // 2
    k_detect<<<1, 32>>>(ei, n);                                      // 3
    {
        dim3 grid(512 / 128, (n + 127) / 128);                       // 4  <-- profiled
        k_bmma<128, false, false><<<grid, 256, SM128>>>(as1, ad1, nullptr, 8, 0, n, 512, 256);
    }

    // --- CSR build ---
    k_initdeg<<<(n + 255) / 256, 256>>>(n);
    k_hist<<<(E + 255) / 256, 256>>>(ei, E, n);
    k_scanA<<<nblk, 1024>>>(n);
    k_scanB<<<1, 32>>>(nblk, n);
    k_scanC<<<(n + 255) / 256, 256>>>(n);
    k_fill<<<(E + n + 255) / 256, 256>>>(ei, E, n);

    // layer 1 gather (split output -> layer-2 GEMM A)
    k_gather4<8, true, true><<<(n * 32 + 255) / 256, 256>>>(b1, bn1g, bn1b, bn1m, bn1v, 1, n);

    // layer 2: H=4 (tensor GEMM, fused attn)
    k_cvtB<<<(64 * 64 + 255) / 256, 256>>>(W2, 64 * 64);
    {
        dim3 grid(256 / 128, (n + 127) / 128);
        k_bmma<128, false, false><<<grid, 256, SM128>>>(as2, ad2, nullptr, 4, 0, n, 256, 64);
    }
    // layer 2 gather (split output -> layer-3 GEMM A)
    k_gather4<4, true, true><<<(n * 32 + 255) / 256, 256>>>(b2, bn2g, bn2b, bn2m, bn2v, 2, n);

    // layer 3: H=1 projection on tensor cores, fused H=1 attn epilogue
    k_cvtB<<<(64 * 16 + 255) / 256, 256>>>(W3, 64 * 16);
    {
        dim3 grid(1, (n + 127) / 128);
        k_bmma<64, false, false><<<grid, 256, SM64>>>(as3, ad3, nullptr, 1, 0, n, 64, 64);
    }
    // layer 3 gather (split output -> classifier GEMM A)
    k_gather1<true><<<(n * 32 + 255) / 256, 256>>>(b3, 1, n);

    // classifier GEMM1 on tensor cores: f2 = relu(f1 @ cW1 + cb1)
    k_cvtB<<<(64 * 16 + 255) / 256, 256>>>(cW1, 64 * 16);
    {
        dim3 grid(1, (n + 127) / 128);
        k_bmma<64, true, true><<<grid, 256, SM64>>>(nullptr, nullptr, cb1, 1, 2, n, 64, 64);
    }
    // logits + softmax (fp32, proven)
    {
        dim3 grid(1, (n + 63) / 64);
        k_sgemm<true, false, true><<<grid, 256>>>(nullptr, cW2, cb2, out, 2, 0, n, 50, 64);
    }
}

// round 16
// speedup vs baseline: 1.1261x; 1.1261x over previous
#include <cuda_runtime.h>
#include <cuda_bf16.h>
#include <math.h>

// ---------------- scratch (device globals; no runtime allocation) -------------
__device__ float g_h[(size_t)50000 * 512];
__device__ float g_as[50000 * 8];
__device__ float g_ad[50000 * 8];
__device__ float g_f1[50000 * 64];
__device__ float g_f2[50000 * 64];
__device__ int   g_deg[50000];
__device__ int   g_rowptr[50001];
__device__ int   g_wp[50000];
__device__ int   g_col[450000];
__device__ int   g_is32;
__device__ int   g_bsum[128];
__device__ int   g_boff[128];
__device__ __nv_bfloat16 g_ahi[(size_t)50000 * 256];
__device__ __nv_bfloat16 g_alo[(size_t)50000 * 256];
__device__ __nv_bfloat16 g_bhi[160000];
__device__ __nv_bfloat16 g_blo[160000];

// weight offsets inside g_bhi/g_blo (elements)
#define OFF_W1  0
#define OFF_W2  131072
#define OFF_W3  147456
#define OFF_CW1 151552

__device__ __forceinline__ float* selbuf(int s) {
    if (s == 0) return g_h;
    if (s == 1) return g_f1;
    return g_f2;
}

__device__ __forceinline__ int edge_at(const void* ei, long long idx, int is32) {
    return is32 ? ((const int*)ei)[idx] : (int)((const long long*)ei)[idx];
}

// ---------------- dtype detection ------------
__global__ void k_detect(const void* __restrict__ ei, int n) {
    if (threadIdx.x != 0 || blockIdx.x != 0) return;
    const long long* p = (const long long*)ei;
    int bad = 0;
    for (int i = 0; i < 64; i++) {
        long long v = p[i];
        if (v < 0 || v >= (long long)n) bad = 1;
    }
    g_is32 = bad;
}

// ---------------- CSR build -------------
__global__ void k_initdeg(int n) {
    int i = blockIdx.x * blockDim.x + threadIdx.x;
    if (i < n) g_deg[i] = 1;
}

__global__ void k_hist(const void* __restrict__ ei, int E, int n) {
    int i = blockIdx.x * blockDim.x + threadIdx.x;
    if (i >= E) return;
    int v = edge_at(ei, (long long)E + i, g_is32);
    if ((unsigned)v < (unsigned)n) atomicAdd(&g_deg[v], 1);
}

__global__ void k_scanA(int n) {
    __shared__ int sh[32];
    int t = threadIdx.x;
    int idx = blockIdx.x * 1024 + t;
    int v = (idx < n) ? g_deg[idx] : 0;
    int x = v;
    #pragma unroll
    for (int o = 1; o < 32; o <<= 1) {
        int y = __shfl_up_sync(0xffffffffu, x, o);
        if ((t & 31) >= o) x += y;
    }
    if ((t & 31) == 31) sh[t >> 5] = x;
    __syncthreads();
    if (t < 32) {
        int y = sh[t];
        #pragma unroll
        for (int o = 1; o < 32; o <<= 1) {
            int z = __shfl_up_sync(0xffffffffu, y, o);
            if (t >= o) y += z;
        }
        sh[t] = y;
    }
    __syncthreads();
    int off = ((t >> 5) > 0) ? sh[(t >> 5) - 1] : 0;
    int excl = x - v + off;
    if (idx < n) g_rowptr[idx] = excl;
    if (t == 1023) g_bsum[blockIdx.x] = excl + v;
}

__global__ void k_scanB(int nb, int n) {
    if (threadIdx.x != 0) return;
    int acc = 0;
    for (int i = 0; i < nb; i++) { int x = g_bsum[i]; g_boff[i] = acc; acc += x; }
    g_rowptr[n] = acc;
}

__global__ void k_scanC(int n) {
    int idx = blockIdx.x * blockDim.x + threadIdx.x;
    if (idx >= n) return;
    int v = g_rowptr[idx] + g_boff[idx >> 10];
    g_rowptr[idx] = v;
    g_wp[idx] = v;
}

__global__ void k_fill(const void* __restrict__ ei, int E, int n) {
    int i = blockIdx.x * blockDim.x + threadIdx.x;
    if (i >= E + n) return;
    int is32 = g_is32;
    int v, s;
    if (i < E) {
        s = edge_at(ei, i, is32);
        v = edge_at(ei, (long long)E + i, is32);
    } else {
        v = s = i - E;
    }
    if ((unsigned)v >= (unsigned)n || (unsigned)s >= (unsigned)n) return;
    int p = atomicAdd(&g_wp[v], 1);
    if ((unsigned)p < (unsigned)(E + n)) g_col[p] = s;
}

// ---------------- bf16 split conversion ----------------
__global__ void k_cvtA(const float* __restrict__ src, int srcsel, int count4) {
    int i = blockIdx.x * blockDim.x + threadIdx.x;
    if (i >= count4) return;
    const float* s = (srcsel < 0) ? src : selbuf(srcsel);
    float4 v = ((const float4*)s)[i];
    __nv_bfloat16 h0 = __float2bfloat16(v.x), h1 = __float2bfloat16(v.y);
    __nv_bfloat16 h2 = __float2bfloat16(v.z), h3 = __float2bfloat16(v.w);
    __nv_bfloat162* ph = (__nv_bfloat162*)g_ahi;
    __nv_bfloat162* pl = (__nv_bfloat162*)g_alo;
    ph[i * 2 + 0] = __nv_bfloat162(h0, h1);
    ph[i * 2 + 1] = __nv_bfloat162(h2, h3);
    pl[i * 2 + 0] = __nv_bfloat162(
        __float2bfloat16(v.x - __bfloat162float(h0)),
        __float2bfloat16(v.y - __bfloat162float(h1)));
    pl[i * 2 + 1] = __nv_bfloat162(
        __float2bfloat16(v.z - __bfloat162float(h2)),
        __float2bfloat16(v.w - __bfloat162float(h3)));
}

// convert all four weight matrices in one launch (float4 granularity)
__global__ void k_cvtW(const float* __restrict__ W1, const float* __restrict__ W2,
                       const float* __restrict__ W3, const float* __restrict__ cW1) {
    // counts (float4): W1 32768, W2 4096, W3 1024, cW1 1024  => 38912 total
    int i = blockIdx.x * blockDim.x + threadIdx.x;
    if (i >= 38912) return;
    const float* src;
    int dst;
    int li;
    if (i < 32768)      { src = W1;  li = i;         dst = OFF_W1  / 4 + li; }
    else if (i < 36864) { src = W2;  li = i - 32768; dst = OFF_W2  / 4 + li; }
    else if (i < 37888) { src = W3;  li = i - 36864; dst = OFF_W3  / 4 + li; }
    else                { src = cW1; li = i - 37888; dst = OFF_CW1 / 4 + li; }
    float4 v = ((const float4*)src)[li];
    __nv_bfloat16 h0 = __float2bfloat16(v.x), h1 = __float2bfloat16(v.y);
    __nv_bfloat16 h2 = __float2bfloat16(v.z), h3 = __float2bfloat16(v.w);
    __nv_bfloat162* ph = (__nv_bfloat162*)g_bhi;
    __nv_bfloat162* pl = (__nv_bfloat162*)g_blo;
    ph[dst * 2 + 0] = __nv_bfloat162(h0, h1);
    ph[dst * 2 + 1] = __nv_bfloat162(h2, h3);
    pl[dst * 2 + 0] = __nv_bfloat162(
        __float2bfloat16(v.x - __bfloat162float(h0)),
        __float2bfloat16(v.y - __bfloat162float(h1)));
    pl[dst * 2 + 1] = __nv_bfloat162(
        __float2bfloat16(v.z - __bfloat162float(h2)),
        __float2bfloat16(v.w - __bfloat162float(h3)));
}

// ---------------- bf16 tensor-core GEMM (fused split fp32, cp.async, BK=16) ----
__device__ __forceinline__ void mma_bf16(float* d, const unsigned* a, const unsigned* b) {
    asm volatile(
        "mma.sync.aligned.m16n8k16.row.col.f32.bf16.bf16.f32 "
        "{%0,%1,%2,%3},{%4,%5,%6,%7},{%8,%9},{%0,%1,%2,%3};\n"
        : "+f"(d[0]), "+f"(d[1]), "+f"(d[2]), "+f"(d[3])
        : "r"(a[0]), "r"(a[1]), "r"(a[2]), "r"(a[3]), "r"(b[0]), "r"(b[1]));
}
__device__ __forceinline__ void ldsm_x4(unsigned* r, unsigned addr) {
    asm volatile("ldmatrix.sync.aligned.m8n8.x4.shared.b16 {%0,%1,%2,%3},[%4];"
        : "=r"(r[0]), "=r"(r[1]), "=r"(r[2]), "=r"(r[3]) : "r"(addr));
}
__device__ __forceinline__ void ldsm_x2t(unsigned* r, unsigned addr) {
    asm volatile("ldmatrix.sync.aligned.m8n8.x2.trans.shared.b16 {%0,%1},[%2];"
        : "=r"(r[0]), "=r"(r[1]) : "r"(addr));
}
__device__ __forceinline__ void cp16(unsigned dst, const void* src, int nbytes) {
    asm volatile("cp.async.cg.shared.global [%0], [%1], 16, %2;"
        :: "r"(dst), "l"(src), "r"(nbytes));
}

#define ASTRIDE 48

// BM=128, BK=16, 256 threads (8 warps). BN=128: warps 2x4; BN=64: warps 4x2.
template <int BN, bool BIAS, bool RELU>
__global__ void __launch_bounds__(256, 2) k_bmma(
        const float* __restrict__ atts, const float* __restrict__ attd,
        const float* __restrict__ bias,
        int bhoff, int H, int csel, int M, int N, int K) {
    constexpr int BSTRIDE = BN * 2 + 16;
    constexpr int WM = (BN == 128) ? 2 : 4;
    constexpr int WN = 8 / WM;
    constexpr int MT = 128 / WM / 16;
    constexpr int NT = BN / WN / 8;
    constexpr int RPW = 128 / WM;
    constexpr int CPW = BN / WN;
    constexpr int BCH = 16 * BN / 8;
    constexpr int HPC = BN / 64;

    float* __restrict__ C = selbuf(csel);
    const __nv_bfloat16* Bhi = g_bhi + bhoff;
    const __nv_bfloat16* Blo = g_blo + bhoff;
    __shared__ __align__(16) unsigned char smAhi[2][128 * ASTRIDE];
    __shared__ __align__(16) unsigned char smAlo[2][128 * ASTRIDE];
    __shared__ __align__(16) unsigned char smBhi[2][16 * BSTRIDE];
    __shared__ __align__(16) unsigned char smBlo[2][16 * BSTRIDE];
    __shared__ float s_att[2][BN];
    __shared__ float red[2][128][2];

    const int tid = threadIdx.x, lane = tid & 31, wid = tid >> 5;
    const int wm = wid % WM, wn = wid / WM;
    const int bm = blockIdx.y * 128, bn = blockIdx.x * BN;
    const int ktiles = K / 16;

    float acc[MT][NT][4];
    #pragma unroll
    for (int i = 0; i < MT; i++)
        #pragma unroll
        for (int j = 0; j < NT; j++)
            #pragma unroll
            for (int q = 0; q < 4; q++) acc[i][j][q] = 0.f;

    const int a_r = tid >> 1, a_cc = tid & 1;
    const int a_gm = bm + a_r;
    const int a_nb = (a_gm < M) ? 16 : 0;
    const int a_gmc = (a_gm < M) ? a_gm : 0;
    const bool bact = (BN == 128) || (tid < BCH);
    const int b_r = (BN == 128) ? (tid >> 4) : (tid >> 3);
    const int b_cc = (BN == 128) ? (tid & 15) : (tid & 7);
    const int b_gn = bn + b_cc * 8;

    auto loadTile = [&](int buf, int kt) {
        int k0 = kt * 16;
        size_t aoff = (size_t)a_gmc * K + k0 + a_cc * 8;
        unsigned dA = a_r * ASTRIDE + a_cc * 16;
        cp16((unsigned)__cvta_generic_to_shared(smAhi[buf]) + dA, g_ahi + aoff, a_nb);
        cp16((unsigned)__cvta_generic_to_shared(smAlo[buf]) + dA, g_alo + aoff, a_nb);
        if (bact) {
            size_t boff = (size_t)(k0 + b_r) * N + b_gn;
            int bnb = (b_gn < N) ? 16 : 0;
            unsigned dB = b_r * BSTRIDE + b_cc * 16;
            cp16((unsigned)__cvta_generic_to_shared(smBhi[buf]) + dB, Bhi + boff, bnb);
            cp16((unsigned)__cvta_generic_to_shared(smBlo[buf]) + dB, Blo + boff, bnb);
        }
        asm volatile("cp.async.commit_group;" ::: "memory");
    };

    const int arow = (lane & 7) + ((lane >> 3) & 1) * 8;
    const int ahalf = (lane >> 4) * 8;
    const int bk = lane & 15;

    loadTile(0, 0);

    for (int it = 0; it < ktiles; it++) {
        int buf = it & 1;
        asm volatile("cp.async.wait_group 0;" ::: "memory");
        __syncthreads();
        if (it + 1 < ktiles) loadTile(buf ^ 1, it + 1);

        unsigned aHiB = (unsigned)__cvta_generic_to_shared(smAhi[buf]);
        unsigned aLoB = (unsigned)__cvta_generic_to_shared(smAlo[buf]);
        unsigned bHiB = (unsigned)__cvta_generic_to_shared(smBhi[buf]);
        unsigned bLoB = (unsigned)__cvta_generic_to_shared(smBlo[buf]);
        unsigned aoff = (wm * RPW + arow) * ASTRIDE + ahalf * 2;
        unsigned boff = bk * BSTRIDE + (wn * CPW) * 2;

        unsigned ahi[MT][4], bhi[NT][2];
        #pragma unroll
        for (int mt = 0; mt < MT; mt++) ldsm_x4(ahi[mt], aHiB + aoff + mt * 16 * ASTRIDE);
        #pragma unroll
        for (int nt = 0; nt < NT; nt++) ldsm_x2t(bhi[nt], bHiB + boff + nt * 16);
        #pragma unroll
        for (int mt = 0; mt < MT; mt++)
            #pragma unroll
            for (int nt = 0; nt < NT; nt++)
                mma_bf16(acc[mt][nt], ahi[mt], bhi[nt]);

        unsigned blo[NT][2];
        #pragma unroll
        for (int nt = 0; nt < NT; nt++) ldsm_x2t(blo[nt], bLoB + boff + nt * 16);
        #pragma unroll
        for (int mt = 0; mt < MT; mt++)
            #pragma unroll
            for (int nt = 0; nt < NT; nt++)
                mma_bf16(acc[mt][nt], ahi[mt], blo[nt]);

        unsigned alo[MT][4];
        #pragma unroll
        for (int mt = 0; mt < MT; mt++) ldsm_x4(alo[mt], aLoB + aoff + mt * 16 * ASTRIDE);
        #pragma unroll
        for (int mt = 0; mt < MT; mt++)
            #pragma unroll
            for (int nt = 0; nt < NT; nt++)
                mma_bf16(acc[mt][nt], alo[mt], bhi[nt]);

        __syncthreads();
    }

    #pragma unroll
    for (int mt = 0; mt < MT; mt++) {
        int r0 = bm + wm * RPW + mt * 16 + (lane >> 2);
        #pragma unroll
        for (int nt = 0; nt < NT; nt++) {
            int cn = bn + wn * CPW + nt * 8 + (lane & 3) * 2;
            if (cn >= N) continue;
            float b0 = 0.f, b1 = 0.f;
            if (BIAS) { b0 = bias[cn]; b1 = bias[cn + 1]; }
            #pragma unroll
            for (int half = 0; half < 2; half++) {
                int r = r0 + half * 8;
                if (r >= M) continue;
                float y0 = acc[mt][nt][half * 2 + 0] + b0;
                float y1 = acc[mt][nt][half * 2 + 1] + b1;
                if (RELU) { y0 = fmaxf(y0, 0.f); y1 = fmaxf(y1, 0.f); }
                *(float2*)(C + (size_t)r * N + cn) = make_float2(y0, y1);
            }
        }
    }

    if (atts != nullptr) {
        if (tid < BN) {
            s_att[0][tid] = atts[bn + tid];
            s_att[1][tid] = attd[bn + tid];
        }
        if (tid < 256) {
            red[0][tid >> 1][tid & 1] = 0.f;
            red[1][tid >> 1][tid & 1] = 0.f;
        }
        __syncthreads();
        int hloc = (wn * CPW) >> 6;
        #pragma unroll
        for (int mt = 0; mt < MT; mt++) {
            #pragma unroll
            for (int half = 0; half < 2; half++) {
                float ps = 0.f, pd = 0.f;
                #pragma unroll
                for (int nt = 0; nt < NT; nt++) {
                    #pragma unroll
                    for (int e = 0; e < 2; e++) {
                        int cl = wn * CPW + nt * 8 + (lane & 3) * 2 + e;
                        float v = acc[mt][nt][half * 2 + e];
                        ps += v * s_att[0][cl];
                        pd += v * s_att[1][cl];
                    }
                }
                ps += __shfl_xor_sync(0xffffffffu, ps, 1);
                ps += __shfl_xor_sync(0xffffffffu, ps, 2);
                pd += __shfl_xor_sync(0xffffffffu, pd, 1);
                pd += __shfl_xor_sync(0xffffffffu, pd, 2);
                if ((lane & 3) == 0) {
                    int rl = wm * RPW + mt * 16 + half * 8 + (lane >> 2);
                    atomicAdd(&red[0][rl][hloc], ps);
                    atomicAdd(&red[1][rl][hloc], pd);
                }
            }
        }
        __syncthreads();
        if (tid < 128) {
            int node = bm + tid;
            if (node < M) {
                int hb = bn >> 6;
                #pragma unroll
                for (int hh = 0; hh < HPC; hh++) {
                    g_as[node * H + hb + hh] = red[0][tid][hh];
                    g_ad[node * H + hb + hh] = red[1][tid][hh];
                }
            }
        }
    }
}

// ---------------- fp32 SGEMM (+optional fused row softmax) ----------------
template <bool BIAS, bool RELU, bool SMAX>
__global__ void k_sgemm(const float* __restrict__ Aext, const float* __restrict__ B,
                        const float* __restrict__ bias, float* __restrict__ outp,
                        int asel, int csel, int M, int N, int K) {
    const float* __restrict__ A = (asel < 0) ? Aext : selbuf(asel);
    float* __restrict__ C = selbuf(csel);
    __shared__ float As[16][68];
    __shared__ float Bs[16][68];
    int tid = threadIdx.x;
    int ty = tid >> 4, tx = tid & 15;
    int bm = blockIdx.y * 64, bn = blockIdx.x * 64;
    int ar = tid >> 2, ac = (tid & 3) << 2;
    int br = tid >> 4, bc = (tid & 15) << 2;
    float acc[4][4];
    #pragma unroll
    for (int i = 0; i < 4; i++)
        #pragma unroll
        for (int j = 0; j < 4; j++) acc[i][j] = 0.f;

    for (int k0 = 0; k0 < K; k0 += 16) {
        int gm = bm + ar;
        float4 av = make_float4(0.f, 0.f, 0.f, 0.f);
        if (gm < M) av = *(const float4*)(A + (size_t)gm * K + k0 + ac);
        As[ac + 0][ar] = av.x; As[ac + 1][ar] = av.y;
        As[ac + 2][ar] = av.z; As[ac + 3][ar] = av.w;

        int gk = k0 + br, gn = bn + bc;
        float4 bv;
        if (((N & 3) == 0) && (gn + 3 < N)) {
            bv = *(const float4*)(B + (size_t)gk * N + gn);
        } else {
            bv.x = (gn + 0 < N) ? B[(size_t)gk * N + gn + 0] : 0.f;
            bv.y = (gn + 1 < N) ? B[(size_t)gk * N + gn + 1] : 0.f;
            bv.z = (gn + 2 < N) ? B[(size_t)gk * N + gn + 2] : 0.f;
            bv.w = (gn + 3 < N) ? B[(size_t)gk * N + gn + 3] : 0.f;
        }
        Bs[br][bc + 0] = bv.x; Bs[br][bc + 1] = bv.y;
        Bs[br][bc + 2] = bv.z; Bs[br][bc + 3] = bv.w;
        __syncthreads();

        #pragma unroll
        for (int kk = 0; kk < 16; kk++) {
            float a[4], b[4];
            #pragma unroll
            for (int i = 0; i < 4; i++) a[i] = As[kk][ty * 4 + i];
            #pragma unroll
            for (int j = 0; j < 4; j++) b[j] = Bs[kk][tx * 4 + j];
            #pragma unroll
            for (int i = 0; i < 4; i++)
                #pragma unroll
                for (int j = 0; j < 4; j++) acc[i][j] += a[i] * b[j];
        }
        __syncthreads();
    }

    if (SMAX) {
        #pragma unroll
        for (int i = 0; i < 4; i++) {
            int row = bm + ty * 4 + i;
            float v[4];
            float mx = -1e30f;
            #pragma unroll
            for (int j = 0; j < 4; j++) {
                int cn = tx * 4 + j;
                v[j] = (cn < N) ? (acc[i][j] + (BIAS ? bias[cn] : 0.f)) : -1e30f;
                mx = fmaxf(mx, v[j]);
            }
            #pragma unroll
            for (int o = 8; o > 0; o >>= 1)
                mx = fmaxf(mx, __shfl_xor_sync(0xffffffffu, mx, o));
            float se = 0.f;
            #pragma unroll
            for (int j = 0; j < 4; j++) {
                v[j] = (tx * 4 + j < N) ? __expf(v[j] - mx) : 0.f;
                se += v[j];
            }
            #pragma unroll
            for (int o = 8; o > 0; o >>= 1)
                se += __shfl_xor_sync(0xffffffffu, se, o);
            float inv = 1.f / se;
            if (row < M) {
                #pragma unroll
                for (int j = 0; j < 4; j++) {
                    int cn = tx * 4 + j;
                    if (cn < N) outp[(size_t)row * N + cn] = v[j] * inv;
                }
            }
        }
    } else {
        #pragma unroll
        for (int i = 0; i < 4; i++) {
            int row = bm + ty * 4 + i;
            if (row >= M) continue;
            #pragma unroll
            for (int j = 0; j < 4; j++) {
                int cn = bn + tx * 4 + j;
                if (cn >= N) continue;
                float v = acc[i][j];
                if (BIAS) v += bias[cn];
                if (RELU) v = fmaxf(v, 0.f);
                C[(size_t)row * N + cn] = v;
            }
        }
    }
}

// ---------------- GAT gather: float4-vectorized, no max pass ----------------
// softmax(e) computed as exp(e)/sum(exp(e)) — identical to max-shifted form.
template <int H, bool BNRELU, bool SPLIT>
__global__ void k_gather4(const float* __restrict__ bias,
                          const float* __restrict__ bng, const float* __restrict__ bnb,
                          const float* __restrict__ bnm, const float* __restrict__ bnv,
                          int osel, int n) {
    constexpr int Q = H / 2;
    float* __restrict__ out = selbuf(osel);
    int w = (blockIdx.x * blockDim.x + threadIdx.x) >> 5;
    int lane = threadIdx.x & 31;
    if (w >= n) return;
    int start = g_rowptr[w], end = g_rowptr[w + 1];
    int c = lane >> 4;

    float aq[Q];
    #pragma unroll
    for (int q = 0; q < Q; q++) aq[q] = g_ad[w * H + c + 2 * q];

    float4 facc[Q];
    float den[Q];
    #pragma unroll
    for (int q = 0; q < Q; q++) { facc[q] = make_float4(0.f, 0.f, 0.f, 0.f); den[q] = 0.f; }

    int j = start;
    for (; j + 2 <= end; j += 2) {
        int s0 = g_col[j], s1 = g_col[j + 1];
        const float4* h0 = (const float4*)(g_h + (size_t)s0 * (H * 64));
        const float4* h1 = (const float4*)(g_h + (size_t)s1 * (H * 64));
        float w0[Q], w1[Q];
        #pragma unroll
        for (int q = 0; q < Q; q++) {
            float e0 = g_as[s0 * H + c + 2 * q] + aq[q];
            e0 = (e0 > 0.f) ? e0 : 0.2f * e0;
            w0[q] = __expf(e0);
            float e1 = g_as[s1 * H + c + 2 * q] + aq[q];
            e1 = (e1 > 0.f) ? e1 : 0.2f * e1;
            w1[q] = __expf(e1);
        }
        float4 v0[Q], v1[Q];
        #pragma unroll
        for (int q = 0; q < Q; q++) { v0[q] = h0[lane + 32 * q]; v1[q] = h1[lane + 32 * q]; }
        #pragma unroll
        for (int q = 0; q < Q; q++) {
            den[q] += w0[q] + w1[q];
            facc[q].x += w0[q] * v0[q].x + w1[q] * v1[q].x;
            facc[q].y += w0[q] * v0[q].y + w1[q] * v1[q].y;
            facc[q].z += w0[q] * v0[q].z + w1[q] * v1[q].z;
            facc[q].w += w0[q] * v0[q].w + w1[q] * v1[q].w;
        }
    }
    if (j < end) {
        int s = g_col[j];
        const float4* hr = (const float4*)(g_h + (size_t)s * (H * 64));
        #pragma unroll
        for (int q = 0; q < Q; q++) {
            float e = g_as[s * H + c + 2 * q] + aq[q];
            e = (e > 0.f) ? e : 0.2f * e;
            float wgt = __expf(e);
            den[q] += wgt;
            float4 v = hr[lane + 32 * q];
            facc[q].x += wgt * v.x; facc[q].y += wgt * v.y;
            facc[q].z += wgt * v.z; facc[q].w += wgt * v.w;
        }
    }

    float4 sum = make_float4(0.f, 0.f, 0.f, 0.f);
    #pragma unroll
    for (int q = 0; q < Q; q++) {
        float inv = 1.f / (den[q] + 1e-16f);
        sum.x += facc[q].x * inv; sum.y += facc[q].y * inv;
        sum.z += facc[q].z * inv; sum.w += facc[q].w * inv;
    }
    sum.x += __shfl_xor_sync(0xffffffffu, sum.x, 16);
    sum.y += __shfl_xor_sync(0xffffffffu, sum.y, 16);
    sum.z += __shfl_xor_sync(0xffffffffu, sum.z, 16);
    sum.w += __shfl_xor_sync(0xffffffffu, sum.w, 16);

    if (c == 0) {
        int ch = (lane & 15) * 4;
        const float invH = 1.f / (float)H;
        float4 bb = *(const float4*)(bias + ch);
        float y[4] = {sum.x * invH + bb.x, sum.y * invH + bb.y,
                      sum.z * invH + bb.z, sum.w * invH + bb.w};
        if (BNRELU) {
            float4 gm_ = *(const float4*)(bng + ch);
            float4 bt = *(const float4*)(bnb + ch);
            float4 mu = *(const float4*)(bnm + ch);
            float4 vr = *(const float4*)(bnv + ch);
            y[0] = fmaxf((y[0] - mu.x) * gm_.x * rsqrtf(vr.x + 1e-5f) + bt.x, 0.f);
            y[1] = fmaxf((y[1] - mu.y) * gm_.y * rsqrtf(vr.y + 1e-5f) + bt.y, 0.f);
            y[2] = fmaxf((y[2] - mu.z) * gm_.z * rsqrtf(vr.z + 1e-5f) + bt.z, 0.f);
            y[3] = fmaxf((y[3] - mu.w) * gm_.w * rsqrtf(vr.w + 1e-5f) + bt.w, 0.f);
        }
        if (SPLIT) {
            size_t base = (size_t)w * 64 + ch;
            #pragma unroll
            for (int k = 0; k < 4; k++) {
                __nv_bfloat16 hi = __float2bfloat16(y[k]);
                g_ahi[base + k] = hi;
                g_alo[base + k] = __float2bfloat16(y[k] - __bfloat162float(hi));
            }
        } else {
            *(float4*)(out + (size_t)w * 64 + ch) = make_float4(y[0], y[1], y[2], y[3]);
        }
    }
}

// ---------------- GAT gather (scalar, H=1; no max pass; optional SPLIT) ----
template <bool SPLIT>
__global__ void k_gather1(const float* __restrict__ bias, int osel, int n) {
    float* __restrict__ out = selbuf(osel);
    int w = (blockIdx.x * blockDim.x + threadIdx.x) >> 5;
    int lane = threadIdx.x & 31;
    if (w >= n) return;
    int start = g_rowptr[w], end = g_rowptr[w + 1];

    float adl = g_ad[w];
    float a0 = 0.f, a1 = 0.f, den = 0.f;
    for (int j = start; j < end; j++) {
        int s = g_col[j];
        float e = g_as[s] + adl;
        e = (e > 0.f) ? e : 0.2f * e;
        float wgt = __expf(e);
        den += wgt;
        const float* hr = g_h + (size_t)s * 64;
        a0 += wgt * hr[lane];
        a1 += wgt * hr[lane + 32];
    }
    float inv = 1.f / (den + 1e-16f);
    float y0 = a0 * inv + bias[lane];
    float y1 = a1 * inv + bias[lane + 32];
    if (SPLIT) {
        size_t base = (size_t)w * 64;
        __nv_bfloat16 h0 = __float2bfloat16(y0);
        __nv_bfloat16 h1 = __float2bfloat16(y1);
        g_ahi[base + lane] = h0;
        g_ahi[base + lane + 32] = h1;
        g_alo[base + lane] = __float2bfloat16(y0 - __bfloat162float(h0));
        g_alo[base + lane + 32] = __float2bfloat16(y1 - __bfloat162float(h1));
    } else {
        out[(size_t)w * 64 + lane] = y0;
        out[(size_t)w * 64 + lane + 32] = y1;
    }
}

// ---------------- host orchestration ----------------
extern "C" void kernel_launch(void* const* d_in, const int* in_sizes, int n_in,
                              void* d_out, int out_size) {
    const float* x   = (const float*)d_in[0];
    const void*  ei  = d_in[1];
    const float* W1  = (const float*)d_in[2];
    const float* as1 = (const float*)d_in[3];
    const float* ad1 = (const float*)d_in[4];
    const float* b1  = (const float*)d_in[5];
    const float* W2  = (const float*)d_in[6];
    const float* as2 = (const float*)d_in[7];
    const float* ad2 = (const float*)d_in[8];
    const float* b2  = (const float*)d_in[9];
    const float* W3  = (const float*)d_in[10];
    const float* as3 = (const float*)d_in[11];
    const float* ad3 = (const float*)d_in[12];
    const float* b3  = (const float*)d_in[13];
    const float* bn1g = (const float*)d_in[14];
    const float* bn1b = (const float*)d_in[15];
    const float* bn1m = (const float*)d_in[16];
    const float* bn1v = (const float*)d_in[17];
    const float* bn2g = (const float*)d_in[18];
    const float* bn2b = (const float*)d_in[19];
    const float* bn2m = (const float*)d_in[20];
    const float* bn2v = (const float*)d_in[21];
    const float* cW1 = (const float*)d_in[22];
    const float* cb1 = (const float*)d_in[23];
    const float* cW2 = (const float*)d_in[24];
    const float* cb2 = (const float*)d_in[25];

    int n = in_sizes[0] / 256;   // 50000
    int E = in_sizes[1] / 2;     // 400000
    float* out = (float*)d_out;
    int nblk = (n + 1023) / 1024;

    // --- layer-1 GEMM first (4th launch = ncu capture slot) ---
    k_cvtA<<<(n * 64 + 255) / 256, 256>>>(x, -1, n * 64);            // 1
    k_cvtW<<<(38912 + 255) / 256, 256>>>(W1, W2, W3, cW1);           // 2 (all weights)
    k_detect<<<1, 32>>>(ei, n);                                      // 3
    {
        dim3 grid(512 / 128, (n + 127) / 128);                       // 4  <-- profiled
        k_bmma<128, false, false><<<grid, 256>>>(as1, ad1, nullptr, OFF_W1, 8, 0, n, 512, 256);
    }

    // --- CSR build ---
    k_initdeg<<<(n + 255) / 256, 256>>>(n);
    k_hist<<<(E + 255) / 256, 256>>>(ei, E, n);
    k_scanA<<<nblk, 1024>>>(n);
    k_scanB<<<1, 32>>>(nblk, n);
    k_scanC<<<(n + 255) / 256, 256>>>(n);
    k_fill<<<(E + n + 255) / 256, 256>>>(ei, E, n);

    // layer 1 gather (split output -> layer-2 GEMM A)
    k_gather4<8, true, true><<<(n * 32 + 255) / 256, 256>>>(b1, bn1g, bn1b, bn1m, bn1v, 1, n);

    // layer 2: H=4
    {
        dim3 grid(256 / 128, (n + 127) / 128);
        k_bmma<128, false, false><<<grid, 256>>>(as2, ad2, nullptr, OFF_W2, 4, 0, n, 256, 64);
    }
    k_gather4<4, true, true><<<(n * 32 + 255) / 256, 256>>>(b2, bn2g, bn2b, bn2m, bn2v, 2, n);

    // layer 3: H=1 projection, fused attn epilogue
    {
        dim3 grid(1, (n + 127) / 128);
        k_bmma<64, false, false><<<grid, 256>>>(as3, ad3, nullptr, OFF_W3, 1, 0, n, 64, 64);
    }
    k_gather1<true><<<(n * 32 + 255) / 256, 256>>>(b3, 1, n);

    // classifier GEMM1: f2 = relu(f1 @ cW1 + cb1)
    {
        dim3 grid(1, (n + 127) / 128);
        k_bmma<64, true, true><<<grid, 256>>>(nullptr, nullptr, cb1, OFF_CW1, 1, 2, n, 64, 64);
    }
    // logits + softmax (fp32, proven)
    {
        dim3 grid(1, (n + 63) / 64);
        k_sgemm<true, false, true><<<grid, 256>>>(nullptr, cW2, cb2, out, 2, 0, n, 50, 64);
    }
}

// round 17
// speedup vs baseline: 1.1316x; 1.0049x over previous
#include <cuda_runtime.h>
#include <cuda_bf16.h>
#include <math.h>

// ---------------- scratch (device globals; no runtime allocation) -------------
__device__ float g_h[(size_t)50000 * 512];
__device__ float g_as[50000 * 8];
__device__ float g_ad[50000 * 8];
__device__ float g_f1[50000 * 64];
__device__ float g_f2[50000 * 64];
__device__ int   g_deg[50000];
__device__ int   g_rowptr[50001];
__device__ int   g_wp[50000];
__device__ int   g_col[450000];
__device__ int   g_is32;
__device__ int   g_bsum[128];
__device__ int   g_boff[128];
__device__ __nv_bfloat16 g_ahi[(size_t)50000 * 256];
__device__ __nv_bfloat16 g_alo[(size_t)50000 * 256];
__device__ __nv_bfloat16 g_bhi[160000];
__device__ __nv_bfloat16 g_blo[160000];

#define OFF_W1  0
#define OFF_W2  131072
#define OFF_W3  147456
#define OFF_CW1 151552

__device__ __forceinline__ float* selbuf(int s) {
    if (s == 0) return g_h;
    if (s == 1) return g_f1;
    return g_f2;
}

__device__ __forceinline__ int edge_at(const void* ei, long long idx, int is32) {
    return is32 ? ((const int*)ei)[idx] : (int)((const long long*)ei)[idx];
}

// ---------------- dtype detection ------------
__global__ void k_detect(const void* __restrict__ ei, int n) {
    if (threadIdx.x != 0 || blockIdx.x != 0) return;
    const long long* p = (const long long*)ei;
    int bad = 0;
    for (int i = 0; i < 64; i++) {
        long long v = p[i];
        if (v < 0 || v >= (long long)n) bad = 1;
    }
    g_is32 = bad;
}

// ---------------- CSR build -------------
__global__ void k_initdeg(int n) {
    int i = blockIdx.x * blockDim.x + threadIdx.x;
    if (i < n) g_deg[i] = 1;
}

__global__ void k_hist(const void* __restrict__ ei, int E, int n) {
    int i = blockIdx.x * blockDim.x + threadIdx.x;
    if (i >= E) return;
    int v = edge_at(ei, (long long)E + i, g_is32);
    if ((unsigned)v < (unsigned)n) atomicAdd(&g_deg[v], 1);
}

__global__ void k_scanA(int n) {
    __shared__ int sh[32];
    int t = threadIdx.x;
    int idx = blockIdx.x * 1024 + t;
    int v = (idx < n) ? g_deg[idx] : 0;
    int x = v;
    #pragma unroll
    for (int o = 1; o < 32; o <<= 1) {
        int y = __shfl_up_sync(0xffffffffu, x, o);
        if ((t & 31) >= o) x += y;
    }
    if ((t & 31) == 31) sh[t >> 5] = x;
    __syncthreads();
    if (t < 32) {
        int y = sh[t];
        #pragma unroll
        for (int o = 1; o < 32; o <<= 1) {
            int z = __shfl_up_sync(0xffffffffu, y, o);
            if (t >= o) y += z;
        }
        sh[t] = y;
    }
    __syncthreads();
    int off = ((t >> 5) > 0) ? sh[(t >> 5) - 1] : 0;
    int excl = x - v + off;
    if (idx < n) g_rowptr[idx] = excl;
    if (t == 1023) g_bsum[blockIdx.x] = excl + v;
}

__global__ void k_scanB(int nb, int n) {
    if (threadIdx.x != 0) return;
    int acc = 0;
    for (int i = 0; i < nb; i++) { int x = g_bsum[i]; g_boff[i] = acc; acc += x; }
    g_rowptr[n] = acc;
}

__global__ void k_scanC(int n) {
    int idx = blockIdx.x * blockDim.x + threadIdx.x;
    if (idx >= n) return;
    int v = g_rowptr[idx] + g_boff[idx >> 10];
    g_rowptr[idx] = v;
    g_wp[idx] = v;
}

__global__ void k_fill(const void* __restrict__ ei, int E, int n) {
    int i = blockIdx.x * blockDim.x + threadIdx.x;
    if (i >= E + n) return;
    int is32 = g_is32;
    int v, s;
    if (i < E) {
        s = edge_at(ei, i, is32);
        v = edge_at(ei, (long long)E + i, is32);
    } else {
        v = s = i - E;
    }
    if ((unsigned)v >= (unsigned)n || (unsigned)s >= (unsigned)n) return;
    int p = atomicAdd(&g_wp[v], 1);
    if ((unsigned)p < (unsigned)(E + n)) g_col[p] = s;
}

// ---------------- bf16 split conversion ----------------
__global__ void k_cvtA(const float* __restrict__ src, int srcsel, int count4) {
    int i = blockIdx.x * blockDim.x + threadIdx.x;
    if (i >= count4) return;
    const float* s = (srcsel < 0) ? src : selbuf(srcsel);
    float4 v = ((const float4*)s)[i];
    __nv_bfloat16 h0 = __float2bfloat16(v.x), h1 = __float2bfloat16(v.y);
    __nv_bfloat16 h2 = __float2bfloat16(v.z), h3 = __float2bfloat16(v.w);
    __nv_bfloat162* ph = (__nv_bfloat162*)g_ahi;
    __nv_bfloat162* pl = (__nv_bfloat162*)g_alo;
    ph[i * 2 + 0] = __nv_bfloat162(h0, h1);
    ph[i * 2 + 1] = __nv_bfloat162(h2, h3);
    pl[i * 2 + 0] = __nv_bfloat162(
        __float2bfloat16(v.x - __bfloat162float(h0)),
        __float2bfloat16(v.y - __bfloat162float(h1)));
    pl[i * 2 + 1] = __nv_bfloat162(
        __float2bfloat16(v.z - __bfloat162float(h2)),
        __float2bfloat16(v.w - __bfloat162float(h3)));
}

__global__ void k_cvtW(const float* __restrict__ W1, const float* __restrict__ W2,
                       const float* __restrict__ W3, const float* __restrict__ cW1) {
    int i = blockIdx.x * blockDim.x + threadIdx.x;
    if (i >= 38912) return;
    const float* src;
    int dst;
    int li;
    if (i < 32768)      { src = W1;  li = i;         dst = OFF_W1  / 4 + li; }
    else if (i < 36864) { src = W2;  li = i - 32768; dst = OFF_W2  / 4 + li; }
    else if (i < 37888) { src = W3;  li = i - 36864; dst = OFF_W3  / 4 + li; }
    else                { src = cW1; li = i - 37888; dst = OFF_CW1 / 4 + li; }
    float4 v = ((const float4*)src)[li];
    __nv_bfloat16 h0 = __float2bfloat16(v.x), h1 = __float2bfloat16(v.y);
    __nv_bfloat16 h2 = __float2bfloat16(v.z), h3 = __float2bfloat16(v.w);
    __nv_bfloat162* ph = (__nv_bfloat162*)g_bhi;
    __nv_bfloat162* pl = (__nv_bfloat162*)g_blo;
    ph[dst * 2 + 0] = __nv_bfloat162(h0, h1);
    ph[dst * 2 + 1] = __nv_bfloat162(h2, h3);
    pl[dst * 2 + 0] = __nv_bfloat162(
        __float2bfloat16(v.x - __bfloat162float(h0)),
        __float2bfloat16(v.y - __bfloat162float(h1)));
    pl[dst * 2 + 1] = __nv_bfloat162(
        __float2bfloat16(v.z - __bfloat162float(h2)),
        __float2bfloat16(v.w - __bfloat162float(h3)));
}

// ---------------- bf16 tensor-core GEMM (fused split fp32, 3-stage cp.async) ----
__device__ __forceinline__ void mma_bf16(float* d, const unsigned* a, const unsigned* b) {
    asm volatile(
        "mma.sync.aligned.m16n8k16.row.col.f32.bf16.bf16.f32 "
        "{%0,%1,%2,%3},{%4,%5,%6,%7},{%8,%9},{%0,%1,%2,%3};\n"
        : "+f"(d[0]), "+f"(d[1]), "+f"(d[2]), "+f"(d[3])
        : "r"(a[0]), "r"(a[1]), "r"(a[2]), "r"(a[3]), "r"(b[0]), "r"(b[1]));
}
__device__ __forceinline__ void ldsm_x4(unsigned* r, unsigned addr) {
    asm volatile("ldmatrix.sync.aligned.m8n8.x4.shared.b16 {%0,%1,%2,%3},[%4];"
        : "=r"(r[0]), "=r"(r[1]), "=r"(r[2]), "=r"(r[3]) : "r"(addr));
}
__device__ __forceinline__ void ldsm_x2t(unsigned* r, unsigned addr) {
    asm volatile("ldmatrix.sync.aligned.m8n8.x2.trans.shared.b16 {%0,%1},[%2];"
        : "=r"(r[0]), "=r"(r[1]) : "r"(addr));
}
__device__ __forceinline__ void cp16(unsigned dst, const void* src, int nbytes) {
    asm volatile("cp.async.cg.shared.global [%0], [%1], 16, %2;"
        :: "r"(dst), "l"(src), "r"(nbytes));
}

#define ASTRIDE 48

// BM=128, BK=16, 256 threads (8 warps), 3-stage cp.async pipeline (dynamic smem).
template <int BN, bool BIAS, bool RELU>
__global__ void __launch_bounds__(256, 2) k_bmma(
        const float* __restrict__ atts, const float* __restrict__ attd,
        const float* __restrict__ bias,
        int bhoff, int H, int csel, int M, int N, int K) {
    constexpr int BSTRIDE = BN * 2 + 16;
    constexpr int WM = (BN == 128) ? 2 : 4;
    constexpr int WN = 8 / WM;
    constexpr int MT = 128 / WM / 16;
    constexpr int NT = BN / WN / 8;
    constexpr int RPW = 128 / WM;
    constexpr int CPW = BN / WN;
    constexpr int BCH = 16 * BN / 8;
    constexpr int HPC = BN / 64;
    constexpr int ABUF = 128 * ASTRIDE;       // per A buffer (one split part)
    constexpr int BBUF = 16 * BSTRIDE;        // per B buffer (one split part)

    float* __restrict__ C = selbuf(csel);
    const __nv_bfloat16* Bhi = g_bhi + bhoff;
    const __nv_bfloat16* Blo = g_blo + bhoff;
    extern __shared__ __align__(16) unsigned char dyn[];
    unsigned char* smAhi = dyn;                       // [3][ABUF]
    unsigned char* smAlo = smAhi + 3 * ABUF;          // [3][ABUF]
    unsigned char* smBhi = smAlo + 3 * ABUF;          // [3][BBUF]
    unsigned char* smBlo = smBhi + 3 * BBUF;          // [3][BBUF]
    __shared__ float s_att[2][BN];
    __shared__ float red[2][128][2];

    const int tid = threadIdx.x, lane = tid & 31, wid = tid >> 5;
    const int wm = wid % WM, wn = wid / WM;
    const int bm = blockIdx.y * 128, bn = blockIdx.x * BN;
    const int ktiles = K / 16;

    float acc[MT][NT][4];
    #pragma unroll
    for (int i = 0; i < MT; i++)
        #pragma unroll
        for (int j = 0; j < NT; j++)
            #pragma unroll
            for (int q = 0; q < 4; q++) acc[i][j][q] = 0.f;

    const int a_r = tid >> 1, a_cc = tid & 1;
    const int a_gm = bm + a_r;
    const int a_nb = (a_gm < M) ? 16 : 0;
    const int a_gmc = (a_gm < M) ? a_gm : 0;
    const bool bact = (BN == 128) || (tid < BCH);
    const int b_r = (BN == 128) ? (tid >> 4) : (tid >> 3);
    const int b_cc = (BN == 128) ? (tid & 15) : (tid & 7);
    const int b_gn = bn + b_cc * 8;

    auto loadTile = [&](int buf, int kt) {
        int k0 = kt * 16;
        size_t aoff = (size_t)a_gmc * K + k0 + a_cc * 8;
        unsigned dA = buf * ABUF + a_r * ASTRIDE + a_cc * 16;
        cp16((unsigned)__cvta_generic_to_shared(smAhi) + dA, g_ahi + aoff, a_nb);
        cp16((unsigned)__cvta_generic_to_shared(smAlo) + dA, g_alo + aoff, a_nb);
        if (bact) {
            size_t boff = (size_t)(k0 + b_r) * N + b_gn;
            int bnb = (b_gn < N) ? 16 : 0;
            unsigned dB = buf * BBUF + b_r * BSTRIDE + b_cc * 16;
            cp16((unsigned)__cvta_generic_to_shared(smBhi) + dB, Bhi + boff, bnb);
            cp16((unsigned)__cvta_generic_to_shared(smBlo) + dB, Blo + boff, bnb);
        }
        asm volatile("cp.async.commit_group;" ::: "memory");
    };

    const int arow = (lane & 7) + ((lane >> 3) & 1) * 8;
    const int ahalf = (lane >> 4) * 8;
    const int bk = lane & 15;

    loadTile(0, 0);
    if (ktiles > 1) loadTile(1, 1);

    for (int it = 0; it < ktiles; it++) {
        int buf = it % 3;
        if (it + 1 < ktiles) {
            asm volatile("cp.async.wait_group 1;" ::: "memory");
        } else {
            asm volatile("cp.async.wait_group 0;" ::: "memory");
        }
        __syncthreads();
        // buffer (it+2)%3 == buffer (it-1)%3: compute(it-1) finished in all
        // threads before this barrier, so safe to overwrite.
        if (it + 2 < ktiles) loadTile((it + 2) % 3, it + 2);

        unsigned aHiB = (unsigned)__cvta_generic_to_shared(smAhi) + buf * ABUF;
        unsigned aLoB = (unsigned)__cvta_generic_to_shared(smAlo) + buf * ABUF;
        unsigned bHiB = (unsigned)__cvta_generic_to_shared(smBhi) + buf * BBUF;
        unsigned bLoB = (unsigned)__cvta_generic_to_shared(smBlo) + buf * BBUF;
        unsigned aoff = (wm * RPW + arow) * ASTRIDE + ahalf * 2;
        unsigned boff = bk * BSTRIDE + (wn * CPW) * 2;

        unsigned ahi[MT][4], bhi[NT][2];
        #pragma unroll
        for (int mt = 0; mt < MT; mt++) ldsm_x4(ahi[mt], aHiB + aoff + mt * 16 * ASTRIDE);
        #pragma unroll
        for (int nt = 0; nt < NT; nt++) ldsm_x2t(bhi[nt], bHiB + boff + nt * 16);
        #pragma unroll
        for (int mt = 0; mt < MT; mt++)
            #pragma unroll
            for (int nt = 0; nt < NT; nt++)
                mma_bf16(acc[mt][nt], ahi[mt], bhi[nt]);

        unsigned blo[NT][2];
        #pragma unroll
        for (int nt = 0; nt < NT; nt++) ldsm_x2t(blo[nt], bLoB + boff + nt * 16);
        #pragma unroll
        for (int mt = 0; mt < MT; mt++)
            #pragma unroll
            for (int nt = 0; nt < NT; nt++)
                mma_bf16(acc[mt][nt], ahi[mt], blo[nt]);

        unsigned alo[MT][4];
        #pragma unroll
        for (int mt = 0; mt < MT; mt++) ldsm_x4(alo[mt], aLoB + aoff + mt * 16 * ASTRIDE);
        #pragma unroll
        for (int mt = 0; mt < MT; mt++)
            #pragma unroll
            for (int nt = 0; nt < NT; nt++)
                mma_bf16(acc[mt][nt], alo[mt], bhi[nt]);
    }

    #pragma unroll
    for (int mt = 0; mt < MT; mt++) {
        int r0 = bm + wm * RPW + mt * 16 + (lane >> 2);
        #pragma unroll
        for (int nt = 0; nt < NT; nt++) {
            int cn = bn + wn * CPW + nt * 8 + (lane & 3) * 2;
            if (cn >= N) continue;
            float b0 = 0.f, b1 = 0.f;
            if (BIAS) { b0 = bias[cn]; b1 = bias[cn + 1]; }
            #pragma unroll
            for (int half = 0; half < 2; half++) {
                int r = r0 + half * 8;
                if (r >= M) continue;
                float y0 = acc[mt][nt][half * 2 + 0] + b0;
                float y1 = acc[mt][nt][half * 2 + 1] + b1;
                if (RELU) { y0 = fmaxf(y0, 0.f); y1 = fmaxf(y1, 0.f); }
                *(float2*)(C + (size_t)r * N + cn) = make_float2(y0, y1);
            }
        }
    }

    if (atts != nullptr) {
        __syncthreads();   // protect s_att/red reuse vs mainloop smem (disjoint, but cheap)
        if (tid < BN) {
            s_att[0][tid] = atts[bn + tid];
            s_att[1][tid] = attd[bn + tid];
        }
        if (tid < 256) {
            red[0][tid >> 1][tid & 1] = 0.f;
            red[1][tid >> 1][tid & 1] = 0.f;
        }
        __syncthreads();
        int hloc = (wn * CPW) >> 6;
        #pragma unroll
        for (int mt = 0; mt < MT; mt++) {
            #pragma unroll
            for (int half = 0; half < 2; half++) {
                float ps = 0.f, pd = 0.f;
                #pragma unroll
                for (int nt = 0; nt < NT; nt++) {
                    #pragma unroll
                    for (int e = 0; e < 2; e++) {
                        int cl = wn * CPW + nt * 8 + (lane & 3) * 2 + e;
                        float v = acc[mt][nt][half * 2 + e];
                        ps += v * s_att[0][cl];
                        pd += v * s_att[1][cl];
                    }
                }
                ps += __shfl_xor_sync(0xffffffffu, ps, 1);
                ps += __shfl_xor_sync(0xffffffffu, ps, 2);
                pd += __shfl_xor_sync(0xffffffffu, pd, 1);
                pd += __shfl_xor_sync(0xffffffffu, pd, 2);
                if ((lane & 3) == 0) {
                    int rl = wm * RPW + mt * 16 + half * 8 + (lane >> 2);
                    atomicAdd(&red[0][rl][hloc], ps);
                    atomicAdd(&red[1][rl][hloc], pd);
                }
            }
        }
        __syncthreads();
        if (tid < 128) {
            int node = bm + tid;
            if (node < M) {
                int hb = bn >> 6;
                #pragma unroll
                for (int hh = 0; hh < HPC; hh++) {
                    g_as[node * H + hb + hh] = red[0][tid][hh];
                    g_ad[node * H + hb + hh] = red[1][tid][hh];
                }
            }
        }
    }
}

// ---------------- fp32 SGEMM (+optional fused row softmax) ----------------
template <bool BIAS, bool RELU, bool SMAX>
__global__ void k_sgemm(const float* __restrict__ Aext, const float* __restrict__ B,
                        const float* __restrict__ bias, float* __restrict__ outp,
                        int asel, int csel, int M, int N, int K) {
    const float* __restrict__ A = (asel < 0) ? Aext : selbuf(asel);
    float* __restrict__ C = selbuf(csel);
    __shared__ float As[16][68];
    __shared__ float Bs[16][68];
    int tid = threadIdx.x;
    int ty = tid >> 4, tx = tid & 15;
    int bm = blockIdx.y * 64, bn = blockIdx.x * 64;
    int ar = tid >> 2, ac = (tid & 3) << 2;
    int br = tid >> 4, bc = (tid & 15) << 2;
    float acc[4][4];
    #pragma unroll
    for (int i = 0; i < 4; i++)
        #pragma unroll
        for (int j = 0; j < 4; j++) acc[i][j] = 0.f;

    for (int k0 = 0; k0 < K; k0 += 16) {
        int gm = bm + ar;
        float4 av = make_float4(0.f, 0.f, 0.f, 0.f);
        if (gm < M) av = *(const float4*)(A + (size_t)gm * K + k0 + ac);
        As[ac + 0][ar] = av.x; As[ac + 1][ar] = av.y;
        As[ac + 2][ar] = av.z; As[ac + 3][ar] = av.w;

        int gk = k0 + br, gn = bn + bc;
        float4 bv;
        if (((N & 3) == 0) && (gn + 3 < N)) {
            bv = *(const float4*)(B + (size_t)gk * N + gn);
        } else {
            bv.x = (gn + 0 < N) ? B[(size_t)gk * N + gn + 0] : 0.f;
            bv.y = (gn + 1 < N) ? B[(size_t)gk * N + gn + 1] : 0.f;
            bv.z = (gn + 2 < N) ? B[(size_t)gk * N + gn + 2] : 0.f;
            bv.w = (gn + 3 < N) ? B[(size_t)gk * N + gn + 3] : 0.f;
        }
        Bs[br][bc + 0] = bv.x; Bs[br][bc + 1] = bv.y;
        Bs[br][bc + 2] = bv.z; Bs[br][bc + 3] = bv.w;
        __syncthreads();

        #pragma unroll
        for (int kk = 0; kk < 16; kk++) {
            float a[4], b[4];
            #pragma unroll
            for (int i = 0; i < 4; i++) a[i] = As[kk][ty * 4 + i];
            #pragma unroll
            for (int j = 0; j < 4; j++) b[j] = Bs[kk][tx * 4 + j];
            #pragma unroll
            for (int i = 0; i < 4; i++)
                #pragma unroll
                for (int j = 0; j < 4; j++) acc[i][j] += a[i] * b[j];
        }
        __syncthreads();
    }

    if (SMAX) {
        #pragma unroll
        for (int i = 0; i < 4; i++) {
            int row = bm + ty * 4 + i;
            float v[4];
            float mx = -1e30f;
            #pragma unroll
            for (int j = 0; j < 4; j++) {
                int cn = tx * 4 + j;
                v[j] = (cn < N) ? (acc[i][j] + (BIAS ? bias[cn] : 0.f)) : -1e30f;
                mx = fmaxf(mx, v[j]);
            }
            #pragma unroll
            for (int o = 8; o > 0; o >>= 1)
                mx = fmaxf(mx, __shfl_xor_sync(0xffffffffu, mx, o));
            float se = 0.f;
            #pragma unroll
            for (int j = 0; j < 4; j++) {
                v[j] = (tx * 4 + j < N) ? __expf(v[j] - mx) : 0.f;
                se += v[j];
            }
            #pragma unroll
            for (int o = 8; o > 0; o >>= 1)
                se += __shfl_xor_sync(0xffffffffu, se, o);
            float inv = 1.f / se;
            if (row < M) {
                #pragma unroll
                for (int j = 0; j < 4; j++) {
                    int cn = tx * 4 + j;
                    if (cn < N) outp[(size_t)row * N + cn] = v[j] * inv;
                }
            }
        }
    } else {
        #pragma unroll
        for (int i = 0; i < 4; i++) {
            int row = bm + ty * 4 + i;
            if (row >= M) continue;
            #pragma unroll
            for (int j = 0; j < 4; j++) {
                int cn = bn + tx * 4 + j;
                if (cn >= N) continue;
                float v = acc[i][j];
                if (BIAS) v += bias[cn];
                if (RELU) v = fmaxf(v, 0.f);
                C[(size_t)row * N + cn] = v;
            }
        }
    }
}

// ---------------- GAT gather: float4-vectorized, no max pass ----------------
template <int H, bool BNRELU, bool SPLIT>
__global__ void k_gather4(const float* __restrict__ bias,
                          const float* __restrict__ bng, const float* __restrict__ bnb,
                          const float* __restrict__ bnm, const float* __restrict__ bnv,
                          int osel, int n) {
    constexpr int Q = H / 2;
    float* __restrict__ out = selbuf(osel);
    int w = (blockIdx.x * blockDim.x + threadIdx.x) >> 5;
    int lane = threadIdx.x & 31;
    if (w >= n) return;
    int start = g_rowptr[w], end = g_rowptr[w + 1];
    int c = lane >> 4;

    float aq[Q];
    #pragma unroll
    for (int q = 0; q < Q; q++) aq[q] = g_ad[w * H + c + 2 * q];

    float4 facc[Q];
    float den[Q];
    #pragma unroll
    for (int q = 0; q < Q; q++) { facc[q] = make_float4(0.f, 0.f, 0.f, 0.f); den[q] = 0.f; }

    int j = start;
    for (; j + 2 <= end; j += 2) {
        int s0 = g_col[j], s1 = g_col[j + 1];
        const float4* h0 = (const float4*)(g_h + (size_t)s0 * (H * 64));
        const float4* h1 = (const float4*)(g_h + (size_t)s1 * (H * 64));
        float w0[Q], w1[Q];
        #pragma unroll
        for (int q = 0; q < Q; q++) {
            float e0 = g_as[s0 * H + c + 2 * q] + aq[q];
            e0 = (e0 > 0.f) ? e0 : 0.2f * e0;
            w0[q] = __expf(e0);
            float e1 = g_as[s1 * H + c + 2 * q] + aq[q];
            e1 = (e1 > 0.f) ? e1 : 0.2f * e1;
            w1[q] = __expf(e1);
        }
        float4 v0[Q], v1[Q];
        #pragma unroll
        for (int q = 0; q < Q; q++) { v0[q] = h0[lane + 32 * q]; v1[q] = h1[lane + 32 * q]; }
        #pragma unroll
        for (int q = 0; q < Q; q++) {
            den[q] += w0[q] + w1[q];
            facc[q].x += w0[q] * v0[q].x + w1[q] * v1[q].x;
            facc[q].y += w0[q] * v0[q].y + w1[q] * v1[q].y;
            facc[q].z += w0[q] * v0[q].z + w1[q] * v1[q].z;
            facc[q].w += w0[q] * v0[q].w + w1[q] * v1[q].w;
        }
    }
    if (j < end) {
        int s = g_col[j];
        const float4* hr = (const float4*)(g_h + (size_t)s * (H * 64));
        #pragma unroll
        for (int q = 0; q < Q; q++) {
            float e = g_as[s * H + c + 2 * q] + aq[q];
            e = (e > 0.f) ? e : 0.2f * e;
            float wgt = __expf(e);
            den[q] += wgt;
            float4 v = hr[lane + 32 * q];
            facc[q].x += wgt * v.x; facc[q].y += wgt * v.y;
            facc[q].z += wgt * v.z; facc[q].w += wgt * v.w;
        }
    }

    float4 sum = make_float4(0.f, 0.f, 0.f, 0.f);
    #pragma unroll
    for (int q = 0; q < Q; q++) {
        float inv = 1.f / (den[q] + 1e-16f);
        sum.x += facc[q].x * inv; sum.y += facc[q].y * inv;
        sum.z += facc[q].z * inv; sum.w += facc[q].w * inv;
    }
    sum.x += __shfl_xor_sync(0xffffffffu, sum.x, 16);
    sum.y += __shfl_xor_sync(0xffffffffu, sum.y, 16);
    sum.z += __shfl_xor_sync(0xffffffffu, sum.z, 16);
    sum.w += __shfl_xor_sync(0xffffffffu, sum.w, 16);

    if (c == 0) {
        int ch = (lane & 15) * 4;
        const float invH = 1.f / (float)H;
        float4 bb = *(const float4*)(bias + ch);
        float y[4] = {sum.x * invH + bb.x, sum.y * invH + bb.y,
                      sum.z * invH + bb.z, sum.w * invH + bb.w};
        if (BNRELU) {
            float4 gm_ = *(const float4*)(bng + ch);
            float4 bt = *(const float4*)(bnb + ch);
            float4 mu = *(const float4*)(bnm + ch);
            float4 vr = *(const float4*)(bnv + ch);
            y[0] = fmaxf((y[0] - mu.x) * gm_.x * rsqrtf(vr.x + 1e-5f) + bt.x, 0.f);
            y[1] = fmaxf((y[1] - mu.y) * gm_.y * rsqrtf(vr.y + 1e-5f) + bt.y, 0.f);
            y[2] = fmaxf((y[2] - mu.z) * gm_.z * rsqrtf(vr.z + 1e-5f) + bt.z, 0.f);
            y[3] = fmaxf((y[3] - mu.w) * gm_.w * rsqrtf(vr.w + 1e-5f) + bt.w, 0.f);
        }
        if (SPLIT) {
            size_t base = (size_t)w * 64 + ch;
            #pragma unroll
            for (int k = 0; k < 4; k++) {
                __nv_bfloat16 hi = __float2bfloat16(y[k]);
                g_ahi[base + k] = hi;
                g_alo[base + k] = __float2bfloat16(y[k] - __bfloat162float(hi));
            }
        } else {
            *(float4*)(out + (size_t)w * 64 + ch) = make_float4(y[0], y[1], y[2], y[3]);
        }
    }
}

// ---------------- GAT gather (scalar, H=1; no max pass; optional SPLIT) ----
template <bool SPLIT>
__global__ void k_gather1(const float* __restrict__ bias, int osel, int n) {
    float* __restrict__ out = selbuf(osel);
    int w = (blockIdx.x * blockDim.x + threadIdx.x) >> 5;
    int lane = threadIdx.x & 31;
    if (w >= n) return;
    int start = g_rowptr[w], end = g_rowptr[w + 1];

    float adl = g_ad[w];
    float a0 = 0.f, a1 = 0.f, den = 0.f;
    for (int j = start; j < end; j++) {
        int s = g_col[j];
        float e = g_as[s] + adl;
        e = (e > 0.f) ? e : 0.2f * e;
        float wgt = __expf(e);
        den += wgt;
        const float* hr = g_h + (size_t)s * 64;
        a0 += wgt * hr[lane];
        a1 += wgt * hr[lane + 32];
    }
    float inv = 1.f / (den + 1e-16f);
    float y0 = a0 * inv + bias[lane];
    float y1 = a1 * inv + bias[lane + 32];
    if (SPLIT) {
        size_t base = (size_t)w * 64;
        __nv_bfloat16 h0 = __float2bfloat16(y0);
        __nv_bfloat16 h1 = __float2bfloat16(y1);
        g_ahi[base + lane] = h0;
        g_ahi[base + lane + 32] = h1;
        g_alo[base + lane] = __float2bfloat16(y0 - __bfloat162float(h0));
        g_alo[base + lane + 32] = __float2bfloat16(y1 - __bfloat162float(h1));
    } else {
        out[(size_t)w * 64 + lane] = y0;
        out[(size_t)w * 64 + lane + 32] = y1;
    }
}

// ---------------- host orchestration ----------------
extern "C" void kernel_launch(void* const* d_in, const int* in_sizes, int n_in,
                              void* d_out, int out_size) {
    const float* x   = (const float*)d_in[0];
    const void*  ei  = d_in[1];
    const float* W1  = (const float*)d_in[2];
    const float* as1 = (const float*)d_in[3];
    const float* ad1 = (const float*)d_in[4];
    const float* b1  = (const float*)d_in[5];
    const float* W2  = (const float*)d_in[6];
    const float* as2 = (const float*)d_in[7];
    const float* ad2 = (const float*)d_in[8];
    const float* b2  = (const float*)d_in[9];
    const float* W3  = (const float*)d_in[10];
    const float* as3 = (const float*)d_in[11];
    const float* ad3 = (const float*)d_in[12];
    const float* b3  = (const float*)d_in[13];
    const float* bn1g = (const float*)d_in[14];
    const float* bn1b = (const float*)d_in[15];
    const float* bn1m = (const float*)d_in[16];
    const float* bn1v = (const float*)d_in[17];
    const float* bn2g = (const float*)d_in[18];
    const float* bn2b = (const float*)d_in[19];
    const float* bn2m = (const float*)d_in[20];
    const float* bn2v = (const float*)d_in[21];
    const float* cW1 = (const float*)d_in[22];
    const float* cb1 = (const float*)d_in[23];
    const float* cW2 = (const float*)d_in[24];
    const float* cb2 = (const float*)d_in[25];

    int n = in_sizes[0] / 256;   // 50000
    int E = in_sizes[1] / 2;     // 400000
    float* out = (float*)d_out;
    int nblk = (n + 1023) / 1024;

    // 3-stage dynamic smem sizes
    const int SM128 = 3 * 2 * 128 * 48 + 3 * 2 * 16 * (128 * 2 + 16);  // 62976
    const int SM64  = 3 * 2 * 128 * 48 + 3 * 2 * 16 * (64 * 2 + 16);   // 50688
    cudaFuncSetAttribute(k_bmma<128, false, false>,
                         cudaFuncAttributeMaxDynamicSharedMemorySize, SM128);
    cudaFuncSetAttribute(k_bmma<64, false, false>,
                         cudaFuncAttributeMaxDynamicSharedMemorySize, SM64);
    cudaFuncSetAttribute(k_bmma<64, true, true>,
                         cudaFuncAttributeMaxDynamicSharedMemorySize, SM64);

    // --- layer-1 GEMM first (4th launch = ncu capture slot) ---
    k_cvtA<<<(n * 64 + 255) / 256, 256>>>(x, -1, n * 64);            // 1
    k_cvtW<<<(38912 + 255) / 256, 256>>>(W1, W2, W3, cW1);           // 2
    k_detect<<<1, 32>>>(ei, n);                                      // 3
    {
        dim3 grid(512 / 128, (n + 127) / 128);                       // 4  <-- profiled
        k_bmma<128, false, false><<<grid, 256, SM128>>>(as1, ad1, nullptr, OFF_W1, 8, 0, n, 512, 256);
    }

    // --- CSR build ---
    k_initdeg<<<(n + 255) / 256, 256>>>(n);
    k_hist<<<(E + 255) / 256, 256>>>(ei, E, n);
    k_scanA<<<nblk, 1024>>>(n);
    k_scanB<<<1, 32>>>(nblk, n);
    k_scanC<<<(n + 255) / 256, 256>>>(n);
    k_fill<<<(E + n + 255) / 256, 256>>>(ei, E, n);

    // layer 1 gather (split output -> layer-2 GEMM A)
    k_gather4<8, true, true><<<(n * 32 + 255) / 256, 256>>>(b1, bn1g, bn1b, bn1m, bn1v, 1, n);

    // layer 2: H=4
    {
        dim3 grid(256 / 128, (n + 127) / 128);
        k_bmma<128, false, false><<<grid, 256, SM128>>>(as2, ad2, nullptr, OFF_W2, 4, 0, n, 256, 64);
    }
    k_gather4<4, true, true><<<(n * 32 + 255) / 256, 256>>>(b2, bn2g, bn2b, bn2m, bn2v, 2, n);

    // layer 3: H=1 projection, fused attn epilogue
    {
        dim3 grid(1, (n + 127) / 128);
        k_bmma<64, false, false><<<grid, 256, SM64>>>(as3, ad3, nullptr, OFF_W3, 1, 0, n, 64, 64);
    }
    k_gather1<true><<<(n * 32 + 255) / 256, 256>>>(b3, 1, n);

    // classifier GEMM1: f2 = relu(f1 @ cW1 + cb1)
    {
        dim3 grid(1, (n + 127) / 128);
        k_bmma<64, true, true><<<grid, 256, SM64>>>(nullptr, nullptr, cb1, OFF_CW1, 1, 2, n, 64, 64);
    }
    // logits + softmax (fp32, proven)
    {
        dim3 grid(1, (n + 63) / 64);
        k_sgemm<true, false, true><<<grid, 256>>>(nullptr, cW2, cb2, out, 2, 0, n, 50, 64);
    }
}